// round 11
// baseline (speedup 1.0000x reference)
#include <cuda_runtime.h>
#include <cuda_bf16.h>
#include <cstdint>

// Problem constants
#define BATCH 8
#define CDIM 512
#define LDIM 4096
#define HEADS 8
#define DHEAD 64
#define HID 512            // HEADS*DHEAD
#define QKV_ROWS 1536      // 3*HID
#define KV_ROWS 1024       // k,v only
#define CSPLIT 32          // n-splits for context partials

// ---------------------------------------------------------------------------
// Scratch (device globals; no allocation allowed)
// ---------------------------------------------------------------------------
__device__ float g_kv[(size_t)BATCH * KV_ROWS * LDIM];          // k rows 0..511, v rows 512..1023
__device__ __nv_bfloat16 g_xt_hi[(size_t)BATCH * LDIM * CDIM];  // x^T
__device__ __nv_bfloat16 g_xt_lo[(size_t)BATCH * LDIM * CDIM];
__device__ __nv_bfloat16 g_w_hi[(size_t)QKV_ROWS * CDIM];
__device__ __nv_bfloat16 g_w_lo[(size_t)QKV_ROWS * CDIM];
__device__ __nv_bfloat16 g_wqT_hi[(size_t)CDIM * HID];          // Wq^T [c][hd]
__device__ __nv_bfloat16 g_wqT_lo[(size_t)CDIM * HID];
__device__ float g_part[(size_t)CSPLIT * BATCH * HEADS * DHEAD * DHEAD];
__device__ float g_ctx[(size_t)BATCH * HEADS * DHEAD * DHEAD];
__device__ __nv_bfloat16 g_M_hi[(size_t)BATCH * HID * HID];
__device__ __nv_bfloat16 g_M_lo[(size_t)BATCH * HID * HID];
__device__ __nv_bfloat16 g_N_hi[(size_t)BATCH * HID * HID];     // N = M @ Wq
__device__ __nv_bfloat16 g_N_lo[(size_t)BATCH * HID * HID];

// ---------------------------------------------------------------------------
// PTX helpers (baseline sm_103 — mma.sync bf16 only)
// ---------------------------------------------------------------------------
__device__ __forceinline__ uint32_t smem_to_u32(const void* smem_ptr) {
    uint32_t addr;
    asm("{ .reg .u64 tmp; cvta.to.shared.u64 tmp, %1; cvt.u32.u64 %0, tmp; }"
        : "=r"(addr) : "l"(smem_ptr));
    return addr;
}

#define SMEM_SWIZZLE_128B(byte_offset) \
    ((uint32_t)(byte_offset) ^ ((((uint32_t)(byte_offset)) >> 3) & 0x70u))

__device__ __forceinline__ void cp_async16(uint32_t dst, const void* src) {
    asm volatile("cp.async.cg.shared.global [%0], [%1], 16;"
                 :: "r"(dst), "l"(src) : "memory");
}
#define CP_ASYNC_COMMIT() asm volatile("cp.async.commit_group;" ::: "memory")
#define CP_ASYNC_WAIT(n)  asm volatile("cp.async.wait_group %0;" :: "n"(n) : "memory")

__device__ __forceinline__ void ldsm4(uint32_t* r, uint32_t addr) {
    asm volatile("ldmatrix.sync.aligned.m8n8.x4.shared.b16 {%0,%1,%2,%3}, [%4];"
                 : "=r"(r[0]), "=r"(r[1]), "=r"(r[2]), "=r"(r[3]) : "r"(addr));
}

__device__ __forceinline__ void mma_bf16(float* c, const uint32_t* a, const uint32_t* b) {
    asm volatile(
        "mma.sync.aligned.m16n8k16.row.col.f32.bf16.bf16.f32 "
        "{%0,%1,%2,%3}, {%4,%5,%6,%7}, {%8,%9}, {%0,%1,%2,%3};"
        : "+f"(c[0]), "+f"(c[1]), "+f"(c[2]), "+f"(c[3])
        : "r"(a[0]), "r"(a[1]), "r"(a[2]), "r"(a[3]), "r"(b[0]), "r"(b[1]));
}

// ---------------------------------------------------------------------------
// Persistent split-bf16 HMMA GEMM: C[M,N] = A[M,K] @ B[N,K]^T (+row bias)
// K = 512 (8 chunks of BK=64). CTA = 128 threads (4 warps), tile 64m x 128n,
// warp tile 32x64. 2-stage cp.async pipeline, 48KB/stage, 2 CTAs/SM.
// Inner loop ordered term-major so consecutive mmas hit DIFFERENT
// accumulators (reuse distance 8 >> HMMA latency).
// If Ohi != null: write split-bf16 output instead of fp32 C.
// ---------------------------------------------------------------------------
#define STAGE_BYTES 49152
#define OFF_AHI 0
#define OFF_ALO 8192
#define OFF_BHI 16384
#define OFF_BLO 32768
#define GEMM_SMEM (2 * STAGE_BYTES)
#define CHUNKS_PER_TILE 8    // K=512 / BK=64

__global__ __launch_bounds__(128, 2)
void mma_gemm_persistent(const __nv_bfloat16* __restrict__ Ahi,
                         const __nv_bfloat16* __restrict__ Alo,
                         const __nv_bfloat16* __restrict__ Bhi,
                         const __nv_bfloat16* __restrict__ Blo,
                         float* __restrict__ C,
                         int ntm, int ntn, int nb, int N, int K,
                         long long sA, long long sB, long long sC,
                         const float* __restrict__ bias,
                         __nv_bfloat16* __restrict__ Ohi,
                         __nv_bfloat16* __restrict__ Olo)
{
    extern __shared__ char smem[];
    const uint32_t sbase = smem_to_u32(smem);

    const int tid = threadIdx.x;
    const int wid = tid >> 5;
    const int lane = tid & 31;
    const int warp_m = wid >> 1;       // 0..1 (32 rows each)
    const int warp_n = wid & 1;        // 0..1 (64 cols each)

    const int ntiles = ntm * ntn * nb;
    const int my_ntiles = (ntiles - (int)blockIdx.x + (int)gridDim.x - 1) / (int)gridDim.x;
    if (my_ntiles <= 0) return;
    const int my_nchunks = my_ntiles * CHUNKS_PER_TILE;

    auto load_chunk = [&](int k) {
        const int t = k >> 3;
        const int tile_lin = (int)blockIdx.x + t * (int)gridDim.x;
        if (tile_lin >= ntiles) { CP_ASYNC_COMMIT(); return; }
        const int nx = tile_lin % ntn;
        const int rest = tile_lin / ntn;
        const int my = rest % ntm;
        const int b = rest / ntm;
        const int bm = my << 6;        // 64-row tiles
        const int bn = nx << 7;        // 128-col tiles
        const int k0 = (k & 7) << 6;
        const __nv_bfloat16* pAhi = Ahi + (long long)b * sA;
        const __nv_bfloat16* pAlo = Alo + (long long)b * sA;
        const __nv_bfloat16* pBhi = Bhi + (long long)b * sB;
        const __nv_bfloat16* pBlo = Blo + (long long)b * sB;
        const uint32_t sb = sbase + (uint32_t)(k & 1) * STAGE_BYTES;
#pragma unroll
        for (int it = 0; it < 4; it++) {
            const int g = it * 128 + tid;
            const int row = g >> 3;
            const int gr = g & 7;
            const uint32_t sw = SMEM_SWIZZLE_128B(row * 128 + gr * 16);
            const long long aoff = (long long)(bm + row) * K + k0 + gr * 8;
            cp_async16(sb + OFF_AHI + sw, pAhi + aoff);
            cp_async16(sb + OFF_ALO + sw, pAlo + aoff);
        }
#pragma unroll
        for (int it = 0; it < 8; it++) {
            const int g = it * 128 + tid;
            const int row = g >> 3;
            const int gr = g & 7;
            const uint32_t sw = SMEM_SWIZZLE_128B(row * 128 + gr * 16);
            const long long boff = (long long)(bn + row) * K + k0 + gr * 8;
            cp_async16(sb + OFF_BHI + sw, pBhi + boff);
            cp_async16(sb + OFF_BLO + sw, pBlo + boff);
        }
        CP_ASYNC_COMMIT();
    };

    float acc[2][8][4];
#pragma unroll
    for (int i = 0; i < 2; i++)
#pragma unroll
        for (int j = 0; j < 8; j++)
#pragma unroll
            for (int r = 0; r < 4; r++) acc[i][j][r] = 0.0f;

    load_chunk(0);
    load_chunk(1);

    for (int k = 0; k < my_nchunks; k++) {
        CP_ASYNC_WAIT(1);
        __syncthreads();

        const uint32_t sb = sbase + (uint32_t)(k & 1) * STAGE_BYTES;
#pragma unroll
        for (int ks = 0; ks < 4; ks++) {
            uint32_t bhi[16], blo[16];
#pragma unroll
            for (int p = 0; p < 4; p++) {
                const int r = warp_n * 64 + p * 16 + ((lane >> 4) & 1) * 8 + (lane & 7);
                const int cb = ks * 32 + ((lane >> 3) & 1) * 16;
                const uint32_t adr = sb + OFF_BHI + SMEM_SWIZZLE_128B(r * 128 + cb);
                ldsm4(bhi + p * 4, adr);
                ldsm4(blo + p * 4, adr + (OFF_BLO - OFF_BHI));
            }
#pragma unroll
            for (int i = 0; i < 2; i++) {
                const int r = warp_m * 32 + i * 16 + ((lane >> 3) & 1) * 8 + (lane & 7);
                const int cb = ks * 32 + ((lane >> 4) & 1) * 16;
                const uint32_t adr = sb + OFF_AHI + SMEM_SWIZZLE_128B(r * 128 + cb);
                uint32_t ahi[4], alo[4];
                ldsm4(ahi, adr);
                ldsm4(alo, adr + (OFF_ALO - OFF_AHI));
                // term-major order: consecutive mmas touch different accs
#pragma unroll
                for (int j = 0; j < 8; j++)
                    mma_bf16(acc[i][j], ahi, bhi + (j >> 1) * 4 + (j & 1) * 2);
#pragma unroll
                for (int j = 0; j < 8; j++)
                    mma_bf16(acc[i][j], ahi, blo + (j >> 1) * 4 + (j & 1) * 2);
#pragma unroll
                for (int j = 0; j < 8; j++)
                    mma_bf16(acc[i][j], alo, bhi + (j >> 1) * 4 + (j & 1) * 2);
            }
        }
        __syncthreads();
        load_chunk(k + 2);   // 2-stage: stage (k&1) free after barrier

        if ((k & 7) == 7) {
            const int t = k >> 3;
            const int tile_lin = (int)blockIdx.x + t * (int)gridDim.x;
            const int nx = tile_lin % ntn;
            const int rest = tile_lin / ntn;
            const int my = rest % ntm;
            const int b = rest / ntm;
            const int bm = my << 6;
            const int bn = nx << 7;
            if (Ohi == nullptr) {
                float* pC = C + (long long)b * sC;
#pragma unroll
                for (int i = 0; i < 2; i++) {
                    const int m0 = bm + warp_m * 32 + i * 16 + (lane >> 2);
                    const float bv0 = bias ? bias[m0] : 0.0f;
                    const float bv1 = bias ? bias[m0 + 8] : 0.0f;
#pragma unroll
                    for (int j = 0; j < 8; j++) {
                        const int n0 = bn + warp_n * 64 + j * 8 + (lane & 3) * 2;
                        float2 v0, v1;
                        v0.x = acc[i][j][0] + bv0;  v0.y = acc[i][j][1] + bv0;
                        v1.x = acc[i][j][2] + bv1;  v1.y = acc[i][j][3] + bv1;
                        *(float2*)(pC + (long long)m0 * N + n0) = v0;
                        *(float2*)(pC + (long long)(m0 + 8) * N + n0) = v1;
                        acc[i][j][0] = 0.0f; acc[i][j][1] = 0.0f;
                        acc[i][j][2] = 0.0f; acc[i][j][3] = 0.0f;
                    }
                }
            } else {
                __nv_bfloat16* pH = Ohi + (long long)b * sC;
                __nv_bfloat16* pL = Olo + (long long)b * sC;
#pragma unroll
                for (int i = 0; i < 2; i++) {
                    const int m0 = bm + warp_m * 32 + i * 16 + (lane >> 2);
#pragma unroll
                    for (int j = 0; j < 8; j++) {
                        const int n0 = bn + warp_n * 64 + j * 8 + (lane & 3) * 2;
#pragma unroll
                        for (int r = 0; r < 4; r++) {
                            const int mm = m0 + (r >> 1) * 8;
                            const int nn = n0 + (r & 1);
                            const float v = acc[i][j][r];
                            const __nv_bfloat16 hi = __float2bfloat16(v);
                            pH[(long long)mm * N + nn] = hi;
                            pL[(long long)mm * N + nn] = __float2bfloat16(v - __bfloat162float(hi));
                            acc[i][j][r] = 0.0f;
                        }
                    }
                }
            }
        }
    }
}

// ---------------------------------------------------------------------------
// Transpose + split-convert: in fp32 [R, L] -> out_hi/out_lo bf16 [L, R]
// ---------------------------------------------------------------------------
__global__ __launch_bounds__(256) void transpose_convert_kernel(
    const float* __restrict__ in,
    __nv_bfloat16* __restrict__ out_hi, __nv_bfloat16* __restrict__ out_lo,
    int R, int L, long long inStride, long long outStride)
{
    const int b = blockIdx.z;
    in += (long long)b * inStride;
    out_hi += (long long)b * outStride;
    out_lo += (long long)b * outStride;

    __shared__ float t[32][33];
    const int r0 = blockIdx.y * 32;
    const int c0 = blockIdx.x * 32;
    const int tx = threadIdx.x & 31;
    const int ty = threadIdx.x >> 5;

#pragma unroll
    for (int i = 0; i < 4; i++)
        t[ty + i * 8][tx] = in[(long long)(r0 + ty + i * 8) * L + c0 + tx];
    __syncthreads();
#pragma unroll
    for (int i = 0; i < 4; i++) {
        const float v = t[tx][ty + i * 8];
        const __nv_bfloat16 hi = __float2bfloat16(v);
        const float lo = v - __bfloat162float(hi);
        const long long o = (long long)(c0 + ty + i * 8) * R + r0 + tx;
        out_hi[o] = hi;
        out_lo[o] = __float2bfloat16(lo);
    }
}

// Plain split-convert
__global__ __launch_bounds__(256) void convert_split_kernel(
    const float* __restrict__ in,
    __nv_bfloat16* __restrict__ hi, __nv_bfloat16* __restrict__ lo, int n)
{
    const int i = blockIdx.x * blockDim.x + threadIdx.x;
    if (i < n) {
        const float v = in[i];
        const __nv_bfloat16 h = __float2bfloat16(v);
        hi[i] = h;
        lo[i] = __float2bfloat16(v - __bfloat162float(h));
    }
}

// ---------------------------------------------------------------------------
// Row softmax over L=4096 on k rows (rows 0..511 of g_kv per batch)
// ---------------------------------------------------------------------------
__global__ __launch_bounds__(256) void softmax_kernel()
{
    const int row = blockIdx.x;
    const int b = row >> 9;
    const int r = row & 511;
    float* p = g_kv + (long long)b * KV_ROWS * LDIM + (long long)r * LDIM;

    const int tid = threadIdx.x;
    __shared__ float red[256];

    float4 v[4];
#pragma unroll
    for (int i = 0; i < 4; i++)
        v[i] = *(const float4*)(p + i * 1024 + tid * 4);

    float vmax = -1e30f;
#pragma unroll
    for (int i = 0; i < 4; i++)
        vmax = fmaxf(vmax, fmaxf(fmaxf(v[i].x, v[i].y), fmaxf(v[i].z, v[i].w)));
    red[tid] = vmax;
    __syncthreads();
    for (int s = 128; s > 0; s >>= 1) {
        if (tid < s) red[tid] = fmaxf(red[tid], red[tid + s]);
        __syncthreads();
    }
    vmax = red[0];
    __syncthreads();

    float lsum = 0.0f;
#pragma unroll
    for (int i = 0; i < 4; i++) {
        v[i].x = expf(v[i].x - vmax); lsum += v[i].x;
        v[i].y = expf(v[i].y - vmax); lsum += v[i].y;
        v[i].z = expf(v[i].z - vmax); lsum += v[i].z;
        v[i].w = expf(v[i].w - vmax); lsum += v[i].w;
    }
    red[tid] = lsum;
    __syncthreads();
    for (int s = 128; s > 0; s >>= 1) {
        if (tid < s) red[tid] += red[tid + s];
        __syncthreads();
    }
    const float inv = 1.0f / red[0];

#pragma unroll
    for (int i = 0; i < 4; i++) {
        v[i].x *= inv; v[i].y *= inv; v[i].z *= inv; v[i].w *= inv;
        *(float4*)(p + i * 1024 + tid * 4) = v[i];
    }
}

// ---------------------------------------------------------------------------
// Context partials + reduce + fold (fp32)
// ---------------------------------------------------------------------------
__global__ __launch_bounds__(256) void context_partial_kernel()
{
    const int split = blockIdx.x;
    const int bh = blockIdx.y;
    const int b = bh >> 3, h = bh & 7;

    const float* kbase = g_kv + (long long)b * KV_ROWS * LDIM + (long long)(h * DHEAD) * LDIM;
    const float* vbase = g_kv + (long long)b * KV_ROWS * LDIM + (long long)(HID + h * DHEAD) * LDIM;

    __shared__ float Ks[64][65];
    __shared__ float Vs[64][65];

    const int tid = threadIdx.x;
    const int td = (tid >> 4) * 4;
    const int te = (tid & 15) * 4;

    float acc[4][4];
#pragma unroll
    for (int i = 0; i < 4; i++)
#pragma unroll
        for (int j = 0; j < 4; j++) acc[i][j] = 0.0f;

    const int chunk = LDIM / CSPLIT;
    for (int sub = 0; sub < chunk / 64; sub++) {
        const int n0 = split * chunk + sub * 64;
        for (int i = tid; i < 1024; i += 256) {
            const int r = i >> 4, c = (i & 15) * 4;
            float4 kv = *(const float4*)(kbase + (long long)r * LDIM + n0 + c);
            Ks[r][c] = kv.x; Ks[r][c + 1] = kv.y; Ks[r][c + 2] = kv.z; Ks[r][c + 3] = kv.w;
            float4 vv = *(const float4*)(vbase + (long long)r * LDIM + n0 + c);
            Vs[r][c] = vv.x; Vs[r][c + 1] = vv.y; Vs[r][c + 2] = vv.z; Vs[r][c + 3] = vv.w;
        }
        __syncthreads();

#pragma unroll 8
        for (int n = 0; n < 64; n++) {
            float kr[4], vr[4];
#pragma unroll
            for (int i = 0; i < 4; i++) kr[i] = Ks[td + i][n];
#pragma unroll
            for (int j = 0; j < 4; j++) vr[j] = Vs[te + j][n];
#pragma unroll
            for (int i = 0; i < 4; i++)
#pragma unroll
                for (int j = 0; j < 4; j++)
                    acc[i][j] = fmaf(kr[i], vr[j], acc[i][j]);
        }
        __syncthreads();
    }

    float* pout = g_part + ((long long)split * 64 + bh) * (DHEAD * DHEAD);
#pragma unroll
    for (int i = 0; i < 4; i++)
#pragma unroll
        for (int j = 0; j < 4; j++)
            pout[(td + i) * DHEAD + (te + j)] = acc[i][j];
}

__global__ __launch_bounds__(256) void reduce_ctx_kernel()
{
    const int i = blockIdx.x * blockDim.x + threadIdx.x;
    const int total = BATCH * HEADS * DHEAD * DHEAD;
    if (i < total) {
        float s = 0.0f;
#pragma unroll
        for (int sp = 0; sp < CSPLIT; sp++)
            s += g_part[(long long)sp * total + i];
        g_ctx[i] = s;
    }
}

// fold: writes split-bf16 M directly (M = w_out-folded context)
__global__ __launch_bounds__(256) void fold_kernel(const float* __restrict__ w_out)
{
    const int oc = blockIdx.x;
    const int bh = blockIdx.y;
    const int b = bh >> 3, h = bh & 7;

    __shared__ float cs[64][65];
    __shared__ float ws[64][65];

    const int tid = threadIdx.x;
    for (int i = tid; i < 4096; i += 256) {
        const int d = i >> 6, e = i & 63;
        cs[d][e] = g_ctx[((long long)bh * 64 + d) * 64 + e];
    }
    for (int i = tid; i < 4096; i += 256) {
        const int r = i >> 6, e = i & 63;
        ws[r][e] = w_out[(long long)(oc * 64 + r) * CDIM + h * 64 + e];
    }
    __syncthreads();

    const int d = tid & 63;
    const int r0 = (tid >> 6) * 16;
    for (int rr = 0; rr < 16; rr++) {
        float s = 0.0f;
#pragma unroll 8
        for (int e = 0; e < 64; e++)
            s = fmaf(ws[r0 + rr][e], cs[d][e], s);
        const long long o = ((long long)b * HID + oc * 64 + r0 + rr) * HID + h * 64 + d;
        const __nv_bfloat16 hi = __float2bfloat16(s);
        g_M_hi[o] = hi;
        g_M_lo[o] = __float2bfloat16(s - __bfloat162float(hi));
    }
}

// ---------------------------------------------------------------------------
extern "C" void kernel_launch(void* const* d_in, const int* in_sizes, int n_in,
                              void* d_out, int out_size)
{
    const float* x     = (const float*)d_in[0];   // [8, 512, 4096]
    const float* w_qkv = (const float*)d_in[1];   // [1536, 512]
    const float* w_out = (const float*)d_in[2];   // [512, 512]
    const float* b_out = (const float*)d_in[3];   // [512]
    float* out = (float*)d_out;                   // [8, 512, 4096]

    float *p_kv;
    __nv_bfloat16 *p_xthi, *p_xtlo, *p_whi, *p_wlo, *p_wqThi, *p_wqTlo;
    __nv_bfloat16 *p_Mhi, *p_Mlo, *p_Nhi, *p_Nlo;
    cudaGetSymbolAddress((void**)&p_kv, g_kv);
    cudaGetSymbolAddress((void**)&p_xthi, g_xt_hi);
    cudaGetSymbolAddress((void**)&p_xtlo, g_xt_lo);
    cudaGetSymbolAddress((void**)&p_whi, g_w_hi);
    cudaGetSymbolAddress((void**)&p_wlo, g_w_lo);
    cudaGetSymbolAddress((void**)&p_wqThi, g_wqT_hi);
    cudaGetSymbolAddress((void**)&p_wqTlo, g_wqT_lo);
    cudaGetSymbolAddress((void**)&p_Mhi, g_M_hi);
    cudaGetSymbolAddress((void**)&p_Mlo, g_M_lo);
    cudaGetSymbolAddress((void**)&p_Nhi, g_N_hi);
    cudaGetSymbolAddress((void**)&p_Nlo, g_N_lo);

    int nsm = 148;
    cudaDeviceGetAttribute(&nsm, cudaDevAttrMultiProcessorCount, 0);
    const int grid = 2 * nsm;

    cudaFuncSetAttribute(mma_gemm_persistent,
                         cudaFuncAttributeMaxDynamicSharedMemorySize, GEMM_SMEM);

    // 0) split-convert W (all rows); transpose+split x; transpose+split Wq
    convert_split_kernel<<<(QKV_ROWS * CDIM + 255) / 256, 256>>>(w_qkv, p_whi, p_wlo, QKV_ROWS * CDIM);
    transpose_convert_kernel<<<dim3(LDIM / 32, CDIM / 32, BATCH), 256>>>(
        x, p_xthi, p_xtlo, CDIM, LDIM,
        (long long)CDIM * LDIM, (long long)LDIM * CDIM);
    transpose_convert_kernel<<<dim3(CDIM / 32, HID / 32, 1), 256>>>(
        w_qkv, p_wqThi, p_wqTlo, HID, CDIM, 0LL, 0LL);

    // 1) kv = W_kv @ x  (rows 512..1535 of W)
    mma_gemm_persistent<<<grid, 128, GEMM_SMEM>>>(
        p_whi + (size_t)HID * CDIM, p_wlo + (size_t)HID * CDIM,
        p_xthi, p_xtlo, p_kv,
        KV_ROWS / 64, LDIM / 128, BATCH, LDIM, CDIM,
        0LL, (long long)LDIM * CDIM, (long long)KV_ROWS * LDIM, nullptr,
        nullptr, nullptr);

    // 2) softmax over L on k rows
    softmax_kernel<<<BATCH * HID, 256>>>();

    // 3) context partials + deterministic reduce
    context_partial_kernel<<<dim3(CSPLIT, BATCH * HEADS), 256>>>();
    {
        const int total = BATCH * HEADS * DHEAD * DHEAD;
        reduce_ctx_kernel<<<(total + 255) / 256, 256>>>();
    }

    // 4) fold w_out with context -> split-bf16 M directly
    fold_kernel<<<dim3(8, BATCH * HEADS), 256>>>(w_out);

    // 5) N = M @ Wq  (split-bf16 in, split-bf16 out)
    mma_gemm_persistent<<<grid, 128, GEMM_SMEM>>>(
        p_Mhi, p_Mlo, p_wqThi, p_wqTlo, nullptr,
        HID / 64, HID / 128, BATCH, HID, CDIM,
        (long long)HID * HID, 0LL, (long long)HID * HID, nullptr,
        p_Nhi, p_Nlo);

    // 6) out = N @ x + b_out
    mma_gemm_persistent<<<grid, 128, GEMM_SMEM>>>(
        p_Nhi, p_Nlo, p_xthi, p_xtlo, out,
        HID / 64, LDIM / 128, BATCH, LDIM, CDIM,
        (long long)HID * HID, (long long)LDIM * CDIM, (long long)HID * LDIM, b_out,
        nullptr, nullptr);
}

// round 13
// speedup vs baseline: 1.1759x; 1.1759x over previous
#include <cuda_runtime.h>
#include <cuda_fp16.h>
#include <cstdint>

// Problem constants
#define BATCH 8
#define CDIM 512
#define LDIM 4096
#define HEADS 8
#define DHEAD 64
#define HID 512            // HEADS*DHEAD
#define QKV_ROWS 1536      // 3*HID
#define KV_ROWS 1024       // k,v only
#define CSPLIT 32          // n-splits for context partials

// ---------------------------------------------------------------------------
// Scratch (device globals; no allocation allowed)
// ---------------------------------------------------------------------------
__device__ float g_kv[(size_t)BATCH * KV_ROWS * LDIM];      // k rows 0..511, v rows 512..1023
__device__ __half g_xt1[(size_t)BATCH * LDIM * CDIM];       // x^T, 1 fp16 limb
__device__ __half g_w1[(size_t)KV_ROWS * CDIM];             // W_kv limb 1
__device__ __half g_w2[(size_t)KV_ROWS * CDIM];             // W_kv limb 2
__device__ __half g_wqT1[(size_t)CDIM * HID];               // Wq^T limb 1
__device__ __half g_wqT2[(size_t)CDIM * HID];               // Wq^T limb 2
__device__ float g_part[(size_t)CSPLIT * BATCH * HEADS * DHEAD * DHEAD];
__device__ float g_ctx[(size_t)BATCH * HEADS * DHEAD * DHEAD];
__device__ __half g_M1[(size_t)BATCH * HID * HID];          // M limbs
__device__ __half g_M2[(size_t)BATCH * HID * HID];
__device__ __half g_N1[(size_t)BATCH * HID * CDIM];         // N = M @ Wq limbs
__device__ __half g_N2[(size_t)BATCH * HID * CDIM];

// ---------------------------------------------------------------------------
// PTX helpers (baseline sm_103 — mma.sync fp16 only)
// ---------------------------------------------------------------------------
__device__ __forceinline__ uint32_t smem_to_u32(const void* smem_ptr) {
    uint32_t addr;
    asm("{ .reg .u64 tmp; cvta.to.shared.u64 tmp, %1; cvt.u32.u64 %0, tmp; }"
        : "=r"(addr) : "l"(smem_ptr));
    return addr;
}

#define SMEM_SWIZZLE_128B(byte_offset) \
    ((uint32_t)(byte_offset) ^ ((((uint32_t)(byte_offset)) >> 3) & 0x70u))

__device__ __forceinline__ void cp_async16(uint32_t dst, const void* src) {
    asm volatile("cp.async.cg.shared.global [%0], [%1], 16;"
                 :: "r"(dst), "l"(src) : "memory");
}
#define CP_ASYNC_COMMIT() asm volatile("cp.async.commit_group;" ::: "memory")
#define CP_ASYNC_WAIT(n)  asm volatile("cp.async.wait_group %0;" :: "n"(n) : "memory")

__device__ __forceinline__ void ldsm4(uint32_t* r, uint32_t addr) {
    asm volatile("ldmatrix.sync.aligned.m8n8.x4.shared.b16 {%0,%1,%2,%3}, [%4];"
                 : "=r"(r[0]), "=r"(r[1]), "=r"(r[2]), "=r"(r[3]) : "r"(addr));
}

__device__ __forceinline__ void mma_f16(float* c, const uint32_t* a, const uint32_t* b) {
    asm volatile(
        "mma.sync.aligned.m16n8k16.row.col.f32.f16.f16.f32 "
        "{%0,%1,%2,%3}, {%4,%5,%6,%7}, {%8,%9}, {%0,%1,%2,%3};"
        : "+f"(c[0]), "+f"(c[1]), "+f"(c[2]), "+f"(c[3])
        : "r"(a[0]), "r"(a[1]), "r"(a[2]), "r"(a[3]), "r"(b[0]), "r"(b[1]));
}

// ---------------------------------------------------------------------------
// Persistent split-fp16 HMMA GEMM: C[M,N] = A[M,K] @ B[N,K]^T (+row bias)
// A given as 2 fp16 limbs (near-exact); B as 1 limb (2-term scheme) or,
// if B2 != null, 2 limbs (3-term: A1B1 + A2B1 + A1B2).
// K = 512 (8 chunks of BK=64). CTA = 128 thr (4 warps), tile 64m x 128n,
// warp tile 32x64. 2-stage cp.async pipeline, 2 CTAs/SM, persistent.
// If O1 != null: write 2-limb fp16 output instead of fp32 C.
// ---------------------------------------------------------------------------
#define STAGE_BYTES 49152
#define OFF_A1 0
#define OFF_A2 8192
#define OFF_B1 16384
#define OFF_B2 32768
#define GEMM_SMEM (2 * STAGE_BYTES)
#define CHUNKS_PER_TILE 8    // K=512 / BK=64

__global__ __launch_bounds__(128, 2)
void mma_gemm_persistent(const __half* __restrict__ A1,
                         const __half* __restrict__ A2,
                         const __half* __restrict__ B1,
                         const __half* __restrict__ B2,
                         float* __restrict__ C,
                         int ntm, int ntn, int nb, int N, int K,
                         long long sA, long long sB, long long sC,
                         const float* __restrict__ bias,
                         __half* __restrict__ O1,
                         __half* __restrict__ O2)
{
    extern __shared__ char smem[];
    const uint32_t sbase = smem_to_u32(smem);

    const int tid = threadIdx.x;
    const int wid = tid >> 5;
    const int lane = tid & 31;
    const int warp_m = wid >> 1;       // 0..1 (32 rows each)
    const int warp_n = wid & 1;        // 0..1 (64 cols each)
    const bool has_b2 = (B2 != nullptr);

    const int ntiles = ntm * ntn * nb;
    const int my_ntiles = (ntiles - (int)blockIdx.x + (int)gridDim.x - 1) / (int)gridDim.x;
    if (my_ntiles <= 0) return;
    const int my_nchunks = my_ntiles * CHUNKS_PER_TILE;

    auto load_chunk = [&](int k) {
        const int t = k >> 3;
        const int tile_lin = (int)blockIdx.x + t * (int)gridDim.x;
        if (tile_lin >= ntiles) { CP_ASYNC_COMMIT(); return; }
        const int nx = tile_lin % ntn;
        const int rest = tile_lin / ntn;
        const int my = rest % ntm;
        const int b = rest / ntm;
        const int bm = my << 6;        // 64-row tiles
        const int bn = nx << 7;        // 128-col tiles
        const int k0 = (k & 7) << 6;
        const __half* pA1 = A1 + (long long)b * sA;
        const __half* pA2 = A2 + (long long)b * sA;
        const __half* pB1 = B1 + (long long)b * sB;
        const uint32_t sb = sbase + (uint32_t)(k & 1) * STAGE_BYTES;
#pragma unroll
        for (int it = 0; it < 4; it++) {
            const int g = it * 128 + tid;
            const int row = g >> 3;
            const int gr = g & 7;
            const uint32_t sw = SMEM_SWIZZLE_128B(row * 128 + gr * 16);
            const long long aoff = (long long)(bm + row) * K + k0 + gr * 8;
            cp_async16(sb + OFF_A1 + sw, pA1 + aoff);
            cp_async16(sb + OFF_A2 + sw, pA2 + aoff);
        }
#pragma unroll
        for (int it = 0; it < 8; it++) {
            const int g = it * 128 + tid;
            const int row = g >> 3;
            const int gr = g & 7;
            const uint32_t sw = SMEM_SWIZZLE_128B(row * 128 + gr * 16);
            const long long boff = (long long)(bn + row) * K + k0 + gr * 8;
            cp_async16(sb + OFF_B1 + sw, pB1 + boff);
        }
        if (has_b2) {
            const __half* pB2 = B2 + (long long)b * sB;
#pragma unroll
            for (int it = 0; it < 8; it++) {
                const int g = it * 128 + tid;
                const int row = g >> 3;
                const int gr = g & 7;
                const uint32_t sw = SMEM_SWIZZLE_128B(row * 128 + gr * 16);
                const long long boff = (long long)(bn + row) * K + k0 + gr * 8;
                cp_async16(sb + OFF_B2 + sw, pB2 + boff);
            }
        }
        CP_ASYNC_COMMIT();
    };

    float acc[2][8][4];
#pragma unroll
    for (int i = 0; i < 2; i++)
#pragma unroll
        for (int j = 0; j < 8; j++)
#pragma unroll
            for (int r = 0; r < 4; r++) acc[i][j][r] = 0.0f;

    load_chunk(0);
    load_chunk(1);

    for (int k = 0; k < my_nchunks; k++) {
        CP_ASYNC_WAIT(1);
        __syncthreads();

        const uint32_t sb = sbase + (uint32_t)(k & 1) * STAGE_BYTES;
#pragma unroll
        for (int ks = 0; ks < 4; ks++) {
            uint32_t b1r[16];
#pragma unroll
            for (int p = 0; p < 4; p++) {
                const int r = warp_n * 64 + p * 16 + ((lane >> 4) & 1) * 8 + (lane & 7);
                const int cb = ks * 32 + ((lane >> 3) & 1) * 16;
                ldsm4(b1r + p * 4, sb + OFF_B1 + SMEM_SWIZZLE_128B(r * 128 + cb));
            }
            uint32_t b2r[16];
            if (has_b2) {
#pragma unroll
                for (int p = 0; p < 4; p++) {
                    const int r = warp_n * 64 + p * 16 + ((lane >> 4) & 1) * 8 + (lane & 7);
                    const int cb = ks * 32 + ((lane >> 3) & 1) * 16;
                    ldsm4(b2r + p * 4, sb + OFF_B2 + SMEM_SWIZZLE_128B(r * 128 + cb));
                }
            }
#pragma unroll
            for (int i = 0; i < 2; i++) {
                const int r = warp_m * 32 + i * 16 + ((lane >> 3) & 1) * 8 + (lane & 7);
                const int cb = ks * 32 + ((lane >> 4) & 1) * 16;
                const uint32_t adr = sb + OFF_A1 + SMEM_SWIZZLE_128B(r * 128 + cb);
                uint32_t a1[4], a2[4];
                ldsm4(a1, adr);
                ldsm4(a2, adr + (OFF_A2 - OFF_A1));
#pragma unroll
                for (int j = 0; j < 8; j++)
                    mma_f16(acc[i][j], a1, b1r + (j >> 1) * 4 + (j & 1) * 2);
#pragma unroll
                for (int j = 0; j < 8; j++)
                    mma_f16(acc[i][j], a2, b1r + (j >> 1) * 4 + (j & 1) * 2);
                if (has_b2) {
#pragma unroll
                    for (int j = 0; j < 8; j++)
                        mma_f16(acc[i][j], a1, b2r + (j >> 1) * 4 + (j & 1) * 2);
                }
            }
        }
        __syncthreads();
        load_chunk(k + 2);   // 2-stage: stage (k&1) free after barrier

        if ((k & 7) == 7) {
            const int t = k >> 3;
            const int tile_lin = (int)blockIdx.x + t * (int)gridDim.x;
            const int nx = tile_lin % ntn;
            const int rest = tile_lin / ntn;
            const int my = rest % ntm;
            const int b = rest / ntm;
            const int bm = my << 6;
            const int bn = nx << 7;
            if (O1 == nullptr) {
                float* pC = C + (long long)b * sC;
#pragma unroll
                for (int i = 0; i < 2; i++) {
                    const int m0 = bm + warp_m * 32 + i * 16 + (lane >> 2);
                    const float bv0 = bias ? bias[m0] : 0.0f;
                    const float bv1 = bias ? bias[m0 + 8] : 0.0f;
#pragma unroll
                    for (int j = 0; j < 8; j++) {
                        const int n0 = bn + warp_n * 64 + j * 8 + (lane & 3) * 2;
                        float2 v0, v1;
                        v0.x = acc[i][j][0] + bv0;  v0.y = acc[i][j][1] + bv0;
                        v1.x = acc[i][j][2] + bv1;  v1.y = acc[i][j][3] + bv1;
                        *(float2*)(pC + (long long)m0 * N + n0) = v0;
                        *(float2*)(pC + (long long)(m0 + 8) * N + n0) = v1;
                        acc[i][j][0] = 0.0f; acc[i][j][1] = 0.0f;
                        acc[i][j][2] = 0.0f; acc[i][j][3] = 0.0f;
                    }
                }
            } else {
                __half* p1 = O1 + (long long)b * sC;
                __half* p2 = O2 + (long long)b * sC;
#pragma unroll
                for (int i = 0; i < 2; i++) {
                    const int m0 = bm + warp_m * 32 + i * 16 + (lane >> 2);
#pragma unroll
                    for (int j = 0; j < 8; j++) {
                        const int n0 = bn + warp_n * 64 + j * 8 + (lane & 3) * 2;
#pragma unroll
                        for (int r = 0; r < 4; r++) {
                            const int mm = m0 + (r >> 1) * 8;
                            const int nn = n0 + (r & 1);
                            const float v = acc[i][j][r];
                            const __half h1 = __float2half_rn(v);
                            p1[(long long)mm * N + nn] = h1;
                            p2[(long long)mm * N + nn] = __float2half_rn(v - __half2float(h1));
                            acc[i][j][r] = 0.0f;
                        }
                    }
                }
            }
        }
    }
}

// ---------------------------------------------------------------------------
// Transpose + fp16 convert (1 limb): in fp32 [R, L] -> out [L, R]
// ---------------------------------------------------------------------------
__global__ __launch_bounds__(256) void transpose_cvt1_kernel(
    const float* __restrict__ in, __half* __restrict__ out,
    int R, int L, long long inStride, long long outStride)
{
    const int b = blockIdx.z;
    in += (long long)b * inStride;
    out += (long long)b * outStride;

    __shared__ float t[32][33];
    const int r0 = blockIdx.y * 32;
    const int c0 = blockIdx.x * 32;
    const int tx = threadIdx.x & 31;
    const int ty = threadIdx.x >> 5;

#pragma unroll
    for (int i = 0; i < 4; i++)
        t[ty + i * 8][tx] = in[(long long)(r0 + ty + i * 8) * L + c0 + tx];
    __syncthreads();
#pragma unroll
    for (int i = 0; i < 4; i++) {
        const float v = t[tx][ty + i * 8];
        out[(long long)(c0 + ty + i * 8) * R + r0 + tx] = __float2half_rn(v);
    }
}

// Transpose + fp16 2-limb split: in fp32 [R, L] -> limbs [L, R]
__global__ __launch_bounds__(256) void transpose_cvt2_kernel(
    const float* __restrict__ in,
    __half* __restrict__ o1, __half* __restrict__ o2, int R, int L)
{
    __shared__ float t[32][33];
    const int r0 = blockIdx.y * 32;
    const int c0 = blockIdx.x * 32;
    const int tx = threadIdx.x & 31;
    const int ty = threadIdx.x >> 5;

#pragma unroll
    for (int i = 0; i < 4; i++)
        t[ty + i * 8][tx] = in[(long long)(r0 + ty + i * 8) * L + c0 + tx];
    __syncthreads();
#pragma unroll
    for (int i = 0; i < 4; i++) {
        const float v = t[tx][ty + i * 8];
        const __half h1 = __float2half_rn(v);
        const long long o = (long long)(c0 + ty + i * 8) * R + r0 + tx;
        o1[o] = h1;
        o2[o] = __float2half_rn(v - __half2float(h1));
    }
}

// Plain fp16 2-limb split
__global__ __launch_bounds__(256) void cvt2_kernel(
    const float* __restrict__ in,
    __half* __restrict__ o1, __half* __restrict__ o2, int n)
{
    const int i = blockIdx.x * blockDim.x + threadIdx.x;
    if (i < n) {
        const float v = in[i];
        const __half h1 = __float2half_rn(v);
        o1[i] = h1;
        o2[i] = __float2half_rn(v - __half2float(h1));
    }
}

// ---------------------------------------------------------------------------
// Row softmax over L=4096 on k rows (rows 0..511 of g_kv per batch)
// ---------------------------------------------------------------------------
__global__ __launch_bounds__(256) void softmax_kernel()
{
    const int row = blockIdx.x;
    const int b = row >> 9;
    const int r = row & 511;
    float* p = g_kv + (long long)b * KV_ROWS * LDIM + (long long)r * LDIM;

    const int tid = threadIdx.x;
    __shared__ float red[256];

    float4 v[4];
#pragma unroll
    for (int i = 0; i < 4; i++)
        v[i] = *(const float4*)(p + i * 1024 + tid * 4);

    float vmax = -1e30f;
#pragma unroll
    for (int i = 0; i < 4; i++)
        vmax = fmaxf(vmax, fmaxf(fmaxf(v[i].x, v[i].y), fmaxf(v[i].z, v[i].w)));
    red[tid] = vmax;
    __syncthreads();
    for (int s = 128; s > 0; s >>= 1) {
        if (tid < s) red[tid] = fmaxf(red[tid], red[tid + s]);
        __syncthreads();
    }
    vmax = red[0];
    __syncthreads();

    float lsum = 0.0f;
#pragma unroll
    for (int i = 0; i < 4; i++) {
        v[i].x = expf(v[i].x - vmax); lsum += v[i].x;
        v[i].y = expf(v[i].y - vmax); lsum += v[i].y;
        v[i].z = expf(v[i].z - vmax); lsum += v[i].z;
        v[i].w = expf(v[i].w - vmax); lsum += v[i].w;
    }
    red[tid] = lsum;
    __syncthreads();
    for (int s = 128; s > 0; s >>= 1) {
        if (tid < s) red[tid] += red[tid + s];
        __syncthreads();
    }
    const float inv = 1.0f / red[0];

#pragma unroll
    for (int i = 0; i < 4; i++) {
        v[i].x *= inv; v[i].y *= inv; v[i].z *= inv; v[i].w *= inv;
        *(float4*)(p + i * 1024 + tid * 4) = v[i];
    }
}

// ---------------------------------------------------------------------------
// Context partials + reduce + fold (fp32)
// ---------------------------------------------------------------------------
__global__ __launch_bounds__(256) void context_partial_kernel()
{
    const int split = blockIdx.x;
    const int bh = blockIdx.y;
    const int b = bh >> 3, h = bh & 7;

    const float* kbase = g_kv + (long long)b * KV_ROWS * LDIM + (long long)(h * DHEAD) * LDIM;
    const float* vbase = g_kv + (long long)b * KV_ROWS * LDIM + (long long)(HID + h * DHEAD) * LDIM;

    __shared__ float Ks[64][65];
    __shared__ float Vs[64][65];

    const int tid = threadIdx.x;
    const int td = (tid >> 4) * 4;
    const int te = (tid & 15) * 4;

    float acc[4][4];
#pragma unroll
    for (int i = 0; i < 4; i++)
#pragma unroll
        for (int j = 0; j < 4; j++) acc[i][j] = 0.0f;

    const int chunk = LDIM / CSPLIT;
    for (int sub = 0; sub < chunk / 64; sub++) {
        const int n0 = split * chunk + sub * 64;
        for (int i = tid; i < 1024; i += 256) {
            const int r = i >> 4, c = (i & 15) * 4;
            float4 kv = *(const float4*)(kbase + (long long)r * LDIM + n0 + c);
            Ks[r][c] = kv.x; Ks[r][c + 1] = kv.y; Ks[r][c + 2] = kv.z; Ks[r][c + 3] = kv.w;
            float4 vv = *(const float4*)(vbase + (long long)r * LDIM + n0 + c);
            Vs[r][c] = vv.x; Vs[r][c + 1] = vv.y; Vs[r][c + 2] = vv.z; Vs[r][c + 3] = vv.w;
        }
        __syncthreads();

#pragma unroll 8
        for (int n = 0; n < 64; n++) {
            float kr[4], vr[4];
#pragma unroll
            for (int i = 0; i < 4; i++) kr[i] = Ks[td + i][n];
#pragma unroll
            for (int j = 0; j < 4; j++) vr[j] = Vs[te + j][n];
#pragma unroll
            for (int i = 0; i < 4; i++)
#pragma unroll
                for (int j = 0; j < 4; j++)
                    acc[i][j] = fmaf(kr[i], vr[j], acc[i][j]);
        }
        __syncthreads();
    }

    float* pout = g_part + ((long long)split * 64 + bh) * (DHEAD * DHEAD);
#pragma unroll
    for (int i = 0; i < 4; i++)
#pragma unroll
        for (int j = 0; j < 4; j++)
            pout[(td + i) * DHEAD + (te + j)] = acc[i][j];
}

__global__ __launch_bounds__(256) void reduce_ctx_kernel()
{
    const int i = blockIdx.x * blockDim.x + threadIdx.x;
    const int total = BATCH * HEADS * DHEAD * DHEAD;
    if (i < total) {
        float s = 0.0f;
#pragma unroll
        for (int sp = 0; sp < CSPLIT; sp++)
            s += g_part[(long long)sp * total + i];
        g_ctx[i] = s;
    }
}

// fold: writes 2-limb fp16 M directly
__global__ __launch_bounds__(256) void fold_kernel(const float* __restrict__ w_out)
{
    const int oc = blockIdx.x;
    const int bh = blockIdx.y;
    const int b = bh >> 3, h = bh & 7;

    __shared__ float cs[64][65];
    __shared__ float ws[64][65];

    const int tid = threadIdx.x;
    for (int i = tid; i < 4096; i += 256) {
        const int d = i >> 6, e = i & 63;
        cs[d][e] = g_ctx[((long long)bh * 64 + d) * 64 + e];
    }
    for (int i = tid; i < 4096; i += 256) {
        const int r = i >> 6, e = i & 63;
        ws[r][e] = w_out[(long long)(oc * 64 + r) * CDIM + h * 64 + e];
    }
    __syncthreads();

    const int d = tid & 63;
    const int r0 = (tid >> 6) * 16;
    for (int rr = 0; rr < 16; rr++) {
        float s = 0.0f;
#pragma unroll 8
        for (int e = 0; e < 64; e++)
            s = fmaf(ws[r0 + rr][e], cs[d][e], s);
        const long long o = ((long long)b * HID + oc * 64 + r0 + rr) * HID + h * 64 + d;
        const __half h1 = __float2half_rn(s);
        g_M1[o] = h1;
        g_M2[o] = __float2half_rn(s - __half2float(h1));
    }
}

// ---------------------------------------------------------------------------
extern "C" void kernel_launch(void* const* d_in, const int* in_sizes, int n_in,
                              void* d_out, int out_size)
{
    const float* x     = (const float*)d_in[0];   // [8, 512, 4096]
    const float* w_qkv = (const float*)d_in[1];   // [1536, 512]
    const float* w_out = (const float*)d_in[2];   // [512, 512]
    const float* b_out = (const float*)d_in[3];   // [512]
    float* out = (float*)d_out;                   // [8, 512, 4096]

    float *p_kv;
    __half *p_xt1, *p_w1, *p_w2, *p_wqT1, *p_wqT2, *p_M1, *p_M2, *p_N1, *p_N2;
    cudaGetSymbolAddress((void**)&p_kv, g_kv);
    cudaGetSymbolAddress((void**)&p_xt1, g_xt1);
    cudaGetSymbolAddress((void**)&p_w1, g_w1);
    cudaGetSymbolAddress((void**)&p_w2, g_w2);
    cudaGetSymbolAddress((void**)&p_wqT1, g_wqT1);
    cudaGetSymbolAddress((void**)&p_wqT2, g_wqT2);
    cudaGetSymbolAddress((void**)&p_M1, g_M1);
    cudaGetSymbolAddress((void**)&p_M2, g_M2);
    cudaGetSymbolAddress((void**)&p_N1, g_N1);
    cudaGetSymbolAddress((void**)&p_N2, g_N2);

    int nsm = 148;
    cudaDeviceGetAttribute(&nsm, cudaDevAttrMultiProcessorCount, 0);
    const int grid = 2 * nsm;

    cudaFuncSetAttribute(mma_gemm_persistent,
                         cudaFuncAttributeMaxDynamicSharedMemorySize, GEMM_SMEM);

    // 0) fp16 splits: W_kv (2 limbs), x^T (1 limb), Wq^T (2 limbs)
    cvt2_kernel<<<(KV_ROWS * CDIM + 255) / 256, 256>>>(
        w_qkv + (size_t)HID * CDIM, p_w1, p_w2, KV_ROWS * CDIM);
    transpose_cvt1_kernel<<<dim3(LDIM / 32, CDIM / 32, BATCH), 256>>>(
        x, p_xt1, CDIM, LDIM, (long long)CDIM * LDIM, (long long)LDIM * CDIM);
    transpose_cvt2_kernel<<<dim3(CDIM / 32, HID / 32, 1), 256>>>(
        w_qkv, p_wqT1, p_wqT2, HID, CDIM);

    // 1) kv = W_kv @ x  (2-term fp16)
    mma_gemm_persistent<<<grid, 128, GEMM_SMEM>>>(
        p_w1, p_w2, p_xt1, nullptr, p_kv,
        KV_ROWS / 64, LDIM / 128, BATCH, LDIM, CDIM,
        0LL, (long long)LDIM * CDIM, (long long)KV_ROWS * LDIM, nullptr,
        nullptr, nullptr);

    // 2) softmax over L on k rows
    softmax_kernel<<<BATCH * HID, 256>>>();

    // 3) context partials + deterministic reduce
    context_partial_kernel<<<dim3(CSPLIT, BATCH * HEADS), 256>>>();
    {
        const int total = BATCH * HEADS * DHEAD * DHEAD;
        reduce_ctx_kernel<<<(total + 255) / 256, 256>>>();
    }

    // 4) fold w_out with context -> 2-limb fp16 M
    fold_kernel<<<dim3(8, BATCH * HEADS), 256>>>(w_out);

    // 5) N = M @ Wq  (3-term fp16; tiny, keeps N near-exact)
    mma_gemm_persistent<<<grid, 128, GEMM_SMEM>>>(
        p_M1, p_M2, p_wqT1, p_wqT2, nullptr,
        HID / 64, CDIM / 128, BATCH, CDIM, HID,
        (long long)HID * HID, 0LL, (long long)HID * CDIM, nullptr,
        p_N1, p_N2);

    // 6) out = N @ x + b_out  (2-term fp16)
    mma_gemm_persistent<<<grid, 128, GEMM_SMEM>>>(
        p_N1, p_N2, p_xt1, nullptr, out,
        HID / 64, LDIM / 128, BATCH, LDIM, CDIM,
        (long long)HID * CDIM, (long long)LDIM * CDIM, (long long)HID * LDIM, b_out,
        nullptr, nullptr);
}

// round 14
// speedup vs baseline: 1.3541x; 1.1516x over previous
#include <cuda_runtime.h>
#include <cuda_fp16.h>
#include <cstdint>

// Problem constants
#define BATCH 8
#define CDIM 512
#define LDIM 4096
#define HEADS 8
#define DHEAD 64
#define HID 512            // HEADS*DHEAD
#define QKV_ROWS 1536      // 3*HID
#define KV_ROWS 1024       // k,v only
#define CSPLIT 32          // n-splits for context partials

// ---------------------------------------------------------------------------
// Scratch (device globals; no allocation allowed)
// ---------------------------------------------------------------------------
__device__ float g_kv[(size_t)BATCH * KV_ROWS * LDIM];      // k rows 0..511, v rows 512..1023
__device__ __half g_xt1[(size_t)BATCH * LDIM * CDIM];       // x^T, 1 fp16 limb
__device__ __half g_w1[(size_t)KV_ROWS * CDIM];             // W_kv, 1 limb
__device__ __half g_wqT1[(size_t)CDIM * HID];               // Wq^T limb 1
__device__ __half g_wqT2[(size_t)CDIM * HID];               // Wq^T limb 2
__device__ float g_part[(size_t)CSPLIT * BATCH * HEADS * DHEAD * DHEAD];
__device__ float g_ctx[(size_t)BATCH * HEADS * DHEAD * DHEAD];
__device__ __half g_M1[(size_t)BATCH * HID * HID];          // M limbs
__device__ __half g_M2[(size_t)BATCH * HID * HID];
__device__ __half g_N1[(size_t)BATCH * HID * CDIM];         // N = M @ Wq limbs
__device__ __half g_N2[(size_t)BATCH * HID * CDIM];

// ---------------------------------------------------------------------------
// PTX helpers (baseline sm_103 — mma.sync fp16 only)
// ---------------------------------------------------------------------------
__device__ __forceinline__ uint32_t smem_to_u32(const void* smem_ptr) {
    uint32_t addr;
    asm("{ .reg .u64 tmp; cvta.to.shared.u64 tmp, %1; cvt.u32.u64 %0, tmp; }"
        : "=r"(addr) : "l"(smem_ptr));
    return addr;
}

#define SMEM_SWIZZLE_128B(byte_offset) \
    ((uint32_t)(byte_offset) ^ ((((uint32_t)(byte_offset)) >> 3) & 0x70u))

__device__ __forceinline__ void cp_async16(uint32_t dst, const void* src) {
    asm volatile("cp.async.cg.shared.global [%0], [%1], 16;"
                 :: "r"(dst), "l"(src) : "memory");
}
#define CP_ASYNC_COMMIT() asm volatile("cp.async.commit_group;" ::: "memory")
#define CP_ASYNC_WAIT(n)  asm volatile("cp.async.wait_group %0;" :: "n"(n) : "memory")

__device__ __forceinline__ void ldsm4(uint32_t* r, uint32_t addr) {
    asm volatile("ldmatrix.sync.aligned.m8n8.x4.shared.b16 {%0,%1,%2,%3}, [%4];"
                 : "=r"(r[0]), "=r"(r[1]), "=r"(r[2]), "=r"(r[3]) : "r"(addr));
}

__device__ __forceinline__ void mma_f16(float* c, const uint32_t* a, const uint32_t* b) {
    asm volatile(
        "mma.sync.aligned.m16n8k16.row.col.f32.f16.f16.f32 "
        "{%0,%1,%2,%3}, {%4,%5,%6,%7}, {%8,%9}, {%0,%1,%2,%3};"
        : "+f"(c[0]), "+f"(c[1]), "+f"(c[2]), "+f"(c[3])
        : "r"(a[0]), "r"(a[1]), "r"(a[2]), "r"(a[3]), "r"(b[0]), "r"(b[1]));
}

// ---------------------------------------------------------------------------
// Persistent fp16 HMMA GEMM: C[M,N] = A[M,K] @ B[N,K]^T (+row bias)
// A: 1 or 2 limbs (A2 may be null). B: 1 or 2 limbs (B2 may be null).
// Terms computed: A1B1 [+ A2B1 if A2] [+ A1B2 if B2].
// K = 512 (8 chunks of BK=64). CTA = 128 thr (4 warps), tile 64m x 128n,
// warp tile 32x64. 2-stage cp.async pipeline, 2 CTAs/SM, persistent.
// If O1 != null: write 2-limb fp16 output instead of fp32 C.
// ---------------------------------------------------------------------------
#define STAGE_BYTES 49152
#define OFF_A1 0
#define OFF_A2 8192
#define OFF_B1 16384
#define OFF_B2 32768
#define GEMM_SMEM (2 * STAGE_BYTES)
#define CHUNKS_PER_TILE 8    // K=512 / BK=64

__global__ __launch_bounds__(128, 2)
void mma_gemm_persistent(const __half* __restrict__ A1,
                         const __half* __restrict__ A2,
                         const __half* __restrict__ B1,
                         const __half* __restrict__ B2,
                         float* __restrict__ C,
                         int ntm, int ntn, int nb, int N, int K,
                         long long sA, long long sB, long long sC,
                         const float* __restrict__ bias,
                         __half* __restrict__ O1,
                         __half* __restrict__ O2)
{
    extern __shared__ char smem[];
    const uint32_t sbase = smem_to_u32(smem);

    const int tid = threadIdx.x;
    const int wid = tid >> 5;
    const int lane = tid & 31;
    const int warp_m = wid >> 1;       // 0..1 (32 rows each)
    const int warp_n = wid & 1;        // 0..1 (64 cols each)
    const bool has_a2 = (A2 != nullptr);
    const bool has_b2 = (B2 != nullptr);

    const int ntiles = ntm * ntn * nb;
    const int my_ntiles = (ntiles - (int)blockIdx.x + (int)gridDim.x - 1) / (int)gridDim.x;
    if (my_ntiles <= 0) return;
    const int my_nchunks = my_ntiles * CHUNKS_PER_TILE;

    auto load_chunk = [&](int k) {
        const int t = k >> 3;
        const int tile_lin = (int)blockIdx.x + t * (int)gridDim.x;
        if (tile_lin >= ntiles) { CP_ASYNC_COMMIT(); return; }
        const int nx = tile_lin % ntn;
        const int rest = tile_lin / ntn;
        const int my = rest % ntm;
        const int b = rest / ntm;
        const int bm = my << 6;        // 64-row tiles
        const int bn = nx << 7;        // 128-col tiles
        const int k0 = (k & 7) << 6;
        const __half* pA1 = A1 + (long long)b * sA;
        const __half* pB1 = B1 + (long long)b * sB;
        const uint32_t sb = sbase + (uint32_t)(k & 1) * STAGE_BYTES;
#pragma unroll
        for (int it = 0; it < 4; it++) {
            const int g = it * 128 + tid;
            const int row = g >> 3;
            const int gr = g & 7;
            const uint32_t sw = SMEM_SWIZZLE_128B(row * 128 + gr * 16);
            const long long aoff = (long long)(bm + row) * K + k0 + gr * 8;
            cp_async16(sb + OFF_A1 + sw, pA1 + aoff);
        }
        if (has_a2) {
            const __half* pA2 = A2 + (long long)b * sA;
#pragma unroll
            for (int it = 0; it < 4; it++) {
                const int g = it * 128 + tid;
                const int row = g >> 3;
                const int gr = g & 7;
                const uint32_t sw = SMEM_SWIZZLE_128B(row * 128 + gr * 16);
                const long long aoff = (long long)(bm + row) * K + k0 + gr * 8;
                cp_async16(sb + OFF_A2 + sw, pA2 + aoff);
            }
        }
#pragma unroll
        for (int it = 0; it < 8; it++) {
            const int g = it * 128 + tid;
            const int row = g >> 3;
            const int gr = g & 7;
            const uint32_t sw = SMEM_SWIZZLE_128B(row * 128 + gr * 16);
            const long long boff = (long long)(bn + row) * K + k0 + gr * 8;
            cp_async16(sb + OFF_B1 + sw, pB1 + boff);
        }
        if (has_b2) {
            const __half* pB2 = B2 + (long long)b * sB;
#pragma unroll
            for (int it = 0; it < 8; it++) {
                const int g = it * 128 + tid;
                const int row = g >> 3;
                const int gr = g & 7;
                const uint32_t sw = SMEM_SWIZZLE_128B(row * 128 + gr * 16);
                const long long boff = (long long)(bn + row) * K + k0 + gr * 8;
                cp_async16(sb + OFF_B2 + sw, pB2 + boff);
            }
        }
        CP_ASYNC_COMMIT();
    };

    float acc[2][8][4];
#pragma unroll
    for (int i = 0; i < 2; i++)
#pragma unroll
        for (int j = 0; j < 8; j++)
#pragma unroll
            for (int r = 0; r < 4; r++) acc[i][j][r] = 0.0f;

    load_chunk(0);
    load_chunk(1);

    for (int k = 0; k < my_nchunks; k++) {
        CP_ASYNC_WAIT(1);
        __syncthreads();

        const uint32_t sb = sbase + (uint32_t)(k & 1) * STAGE_BYTES;
#pragma unroll
        for (int ks = 0; ks < 4; ks++) {
            uint32_t b1r[16];
#pragma unroll
            for (int p = 0; p < 4; p++) {
                const int r = warp_n * 64 + p * 16 + ((lane >> 4) & 1) * 8 + (lane & 7);
                const int cb = ks * 32 + ((lane >> 3) & 1) * 16;
                ldsm4(b1r + p * 4, sb + OFF_B1 + SMEM_SWIZZLE_128B(r * 128 + cb));
            }
            uint32_t b2r[16];
            if (has_b2) {
#pragma unroll
                for (int p = 0; p < 4; p++) {
                    const int r = warp_n * 64 + p * 16 + ((lane >> 4) & 1) * 8 + (lane & 7);
                    const int cb = ks * 32 + ((lane >> 3) & 1) * 16;
                    ldsm4(b2r + p * 4, sb + OFF_B2 + SMEM_SWIZZLE_128B(r * 128 + cb));
                }
            }
#pragma unroll
            for (int i = 0; i < 2; i++) {
                const int r = warp_m * 32 + i * 16 + ((lane >> 3) & 1) * 8 + (lane & 7);
                const int cb = ks * 32 + ((lane >> 4) & 1) * 16;
                const uint32_t adr = sb + OFF_A1 + SMEM_SWIZZLE_128B(r * 128 + cb);
                uint32_t a1[4];
                ldsm4(a1, adr);
#pragma unroll
                for (int j = 0; j < 8; j++)
                    mma_f16(acc[i][j], a1, b1r + (j >> 1) * 4 + (j & 1) * 2);
                if (has_a2) {
                    uint32_t a2[4];
                    ldsm4(a2, adr + (OFF_A2 - OFF_A1));
#pragma unroll
                    for (int j = 0; j < 8; j++)
                        mma_f16(acc[i][j], a2, b1r + (j >> 1) * 4 + (j & 1) * 2);
                }
                if (has_b2) {
#pragma unroll
                    for (int j = 0; j < 8; j++)
                        mma_f16(acc[i][j], a1, b2r + (j >> 1) * 4 + (j & 1) * 2);
                }
            }
        }
        __syncthreads();
        load_chunk(k + 2);   // 2-stage: stage (k&1) free after barrier

        if ((k & 7) == 7) {
            const int t = k >> 3;
            const int tile_lin = (int)blockIdx.x + t * (int)gridDim.x;
            const int nx = tile_lin % ntn;
            const int rest = tile_lin / ntn;
            const int my = rest % ntm;
            const int b = rest / ntm;
            const int bm = my << 6;
            const int bn = nx << 7;
            if (O1 == nullptr) {
                float* pC = C + (long long)b * sC;
#pragma unroll
                for (int i = 0; i < 2; i++) {
                    const int m0 = bm + warp_m * 32 + i * 16 + (lane >> 2);
                    const float bv0 = bias ? bias[m0] : 0.0f;
                    const float bv1 = bias ? bias[m0 + 8] : 0.0f;
#pragma unroll
                    for (int j = 0; j < 8; j++) {
                        const int n0 = bn + warp_n * 64 + j * 8 + (lane & 3) * 2;
                        float2 v0, v1;
                        v0.x = acc[i][j][0] + bv0;  v0.y = acc[i][j][1] + bv0;
                        v1.x = acc[i][j][2] + bv1;  v1.y = acc[i][j][3] + bv1;
                        *(float2*)(pC + (long long)m0 * N + n0) = v0;
                        *(float2*)(pC + (long long)(m0 + 8) * N + n0) = v1;
                        acc[i][j][0] = 0.0f; acc[i][j][1] = 0.0f;
                        acc[i][j][2] = 0.0f; acc[i][j][3] = 0.0f;
                    }
                }
            } else {
                __half* p1 = O1 + (long long)b * sC;
                __half* p2 = O2 + (long long)b * sC;
#pragma unroll
                for (int i = 0; i < 2; i++) {
                    const int m0 = bm + warp_m * 32 + i * 16 + (lane >> 2);
#pragma unroll
                    for (int j = 0; j < 8; j++) {
                        const int n0 = bn + warp_n * 64 + j * 8 + (lane & 3) * 2;
#pragma unroll
                        for (int r = 0; r < 4; r++) {
                            const int mm = m0 + (r >> 1) * 8;
                            const int nn = n0 + (r & 1);
                            const float v = acc[i][j][r];
                            const __half h1 = __float2half_rn(v);
                            p1[(long long)mm * N + nn] = h1;
                            p2[(long long)mm * N + nn] = __float2half_rn(v - __half2float(h1));
                            acc[i][j][r] = 0.0f;
                        }
                    }
                }
            }
        }
    }
}

// ---------------------------------------------------------------------------
// Transpose + fp16 convert (1 limb): in fp32 [R, L] -> out [L, R]
// ---------------------------------------------------------------------------
__global__ __launch_bounds__(256) void transpose_cvt1_kernel(
    const float* __restrict__ in, __half* __restrict__ out,
    int R, int L, long long inStride, long long outStride)
{
    const int b = blockIdx.z;
    in += (long long)b * inStride;
    out += (long long)b * outStride;

    __shared__ float t[32][33];
    const int r0 = blockIdx.y * 32;
    const int c0 = blockIdx.x * 32;
    const int tx = threadIdx.x & 31;
    const int ty = threadIdx.x >> 5;

#pragma unroll
    for (int i = 0; i < 4; i++)
        t[ty + i * 8][tx] = in[(long long)(r0 + ty + i * 8) * L + c0 + tx];
    __syncthreads();
#pragma unroll
    for (int i = 0; i < 4; i++) {
        const float v = t[tx][ty + i * 8];
        out[(long long)(c0 + ty + i * 8) * R + r0 + tx] = __float2half_rn(v);
    }
}

// Transpose + fp16 2-limb split: in fp32 [R, L] -> limbs [L, R]
__global__ __launch_bounds__(256) void transpose_cvt2_kernel(
    const float* __restrict__ in,
    __half* __restrict__ o1, __half* __restrict__ o2, int R, int L)
{
    __shared__ float t[32][33];
    const int r0 = blockIdx.y * 32;
    const int c0 = blockIdx.x * 32;
    const int tx = threadIdx.x & 31;
    const int ty = threadIdx.x >> 5;

#pragma unroll
    for (int i = 0; i < 4; i++)
        t[ty + i * 8][tx] = in[(long long)(r0 + ty + i * 8) * L + c0 + tx];
    __syncthreads();
#pragma unroll
    for (int i = 0; i < 4; i++) {
        const float v = t[tx][ty + i * 8];
        const __half h1 = __float2half_rn(v);
        const long long o = (long long)(c0 + ty + i * 8) * R + r0 + tx;
        o1[o] = h1;
        o2[o] = __float2half_rn(v - __half2float(h1));
    }
}

// Plain fp16 convert (1 limb)
__global__ __launch_bounds__(256) void cvt1_kernel(
    const float* __restrict__ in, __half* __restrict__ o1, int n)
{
    const int i = blockIdx.x * blockDim.x + threadIdx.x;
    if (i < n) o1[i] = __float2half_rn(in[i]);
}

// ---------------------------------------------------------------------------
// Row softmax over L=4096 on k rows (rows 0..511 of g_kv per batch)
// ---------------------------------------------------------------------------
__global__ __launch_bounds__(256) void softmax_kernel()
{
    const int row = blockIdx.x;
    const int b = row >> 9;
    const int r = row & 511;
    float* p = g_kv + (long long)b * KV_ROWS * LDIM + (long long)r * LDIM;

    const int tid = threadIdx.x;
    __shared__ float red[256];

    float4 v[4];
#pragma unroll
    for (int i = 0; i < 4; i++)
        v[i] = *(const float4*)(p + i * 1024 + tid * 4);

    float vmax = -1e30f;
#pragma unroll
    for (int i = 0; i < 4; i++)
        vmax = fmaxf(vmax, fmaxf(fmaxf(v[i].x, v[i].y), fmaxf(v[i].z, v[i].w)));
    red[tid] = vmax;
    __syncthreads();
    for (int s = 128; s > 0; s >>= 1) {
        if (tid < s) red[tid] = fmaxf(red[tid], red[tid + s]);
        __syncthreads();
    }
    vmax = red[0];
    __syncthreads();

    float lsum = 0.0f;
#pragma unroll
    for (int i = 0; i < 4; i++) {
        v[i].x = expf(v[i].x - vmax); lsum += v[i].x;
        v[i].y = expf(v[i].y - vmax); lsum += v[i].y;
        v[i].z = expf(v[i].z - vmax); lsum += v[i].z;
        v[i].w = expf(v[i].w - vmax); lsum += v[i].w;
    }
    red[tid] = lsum;
    __syncthreads();
    for (int s = 128; s > 0; s >>= 1) {
        if (tid < s) red[tid] += red[tid + s];
        __syncthreads();
    }
    const float inv = 1.0f / red[0];

#pragma unroll
    for (int i = 0; i < 4; i++) {
        v[i].x *= inv; v[i].y *= inv; v[i].z *= inv; v[i].w *= inv;
        *(float4*)(p + i * 1024 + tid * 4) = v[i];
    }
}

// ---------------------------------------------------------------------------
// Context partials + reduce + fold (fp32)
// ---------------------------------------------------------------------------
__global__ __launch_bounds__(256) void context_partial_kernel()
{
    const int split = blockIdx.x;
    const int bh = blockIdx.y;
    const int b = bh >> 3, h = bh & 7;

    const float* kbase = g_kv + (long long)b * KV_ROWS * LDIM + (long long)(h * DHEAD) * LDIM;
    const float* vbase = g_kv + (long long)b * KV_ROWS * LDIM + (long long)(HID + h * DHEAD) * LDIM;

    __shared__ float Ks[64][65];
    __shared__ float Vs[64][65];

    const int tid = threadIdx.x;
    const int td = (tid >> 4) * 4;
    const int te = (tid & 15) * 4;

    float acc[4][4];
#pragma unroll
    for (int i = 0; i < 4; i++)
#pragma unroll
        for (int j = 0; j < 4; j++) acc[i][j] = 0.0f;

    const int chunk = LDIM / CSPLIT;
    for (int sub = 0; sub < chunk / 64; sub++) {
        const int n0 = split * chunk + sub * 64;
        for (int i = tid; i < 1024; i += 256) {
            const int r = i >> 4, c = (i & 15) * 4;
            float4 kv = *(const float4*)(kbase + (long long)r * LDIM + n0 + c);
            Ks[r][c] = kv.x; Ks[r][c + 1] = kv.y; Ks[r][c + 2] = kv.z; Ks[r][c + 3] = kv.w;
            float4 vv = *(const float4*)(vbase + (long long)r * LDIM + n0 + c);
            Vs[r][c] = vv.x; Vs[r][c + 1] = vv.y; Vs[r][c + 2] = vv.z; Vs[r][c + 3] = vv.w;
        }
        __syncthreads();

#pragma unroll 8
        for (int n = 0; n < 64; n++) {
            float kr[4], vr[4];
#pragma unroll
            for (int i = 0; i < 4; i++) kr[i] = Ks[td + i][n];
#pragma unroll
            for (int j = 0; j < 4; j++) vr[j] = Vs[te + j][n];
#pragma unroll
            for (int i = 0; i < 4; i++)
#pragma unroll
                for (int j = 0; j < 4; j++)
                    acc[i][j] = fmaf(kr[i], vr[j], acc[i][j]);
        }
        __syncthreads();
    }

    float* pout = g_part + ((long long)split * 64 + bh) * (DHEAD * DHEAD);
#pragma unroll
    for (int i = 0; i < 4; i++)
#pragma unroll
        for (int j = 0; j < 4; j++)
            pout[(td + i) * DHEAD + (te + j)] = acc[i][j];
}

__global__ __launch_bounds__(256) void reduce_ctx_kernel()
{
    const int i = blockIdx.x * blockDim.x + threadIdx.x;
    const int total = BATCH * HEADS * DHEAD * DHEAD;
    if (i < total) {
        float s = 0.0f;
#pragma unroll
        for (int sp = 0; sp < CSPLIT; sp++)
            s += g_part[(long long)sp * total + i];
        g_ctx[i] = s;
    }
}

// fold: writes 2-limb fp16 M directly
__global__ __launch_bounds__(256) void fold_kernel(const float* __restrict__ w_out)
{
    const int oc = blockIdx.x;
    const int bh = blockIdx.y;
    const int b = bh >> 3, h = bh & 7;

    __shared__ float cs[64][65];
    __shared__ float ws[64][65];

    const int tid = threadIdx.x;
    for (int i = tid; i < 4096; i += 256) {
        const int d = i >> 6, e = i & 63;
        cs[d][e] = g_ctx[((long long)bh * 64 + d) * 64 + e];
    }
    for (int i = tid; i < 4096; i += 256) {
        const int r = i >> 6, e = i & 63;
        ws[r][e] = w_out[(long long)(oc * 64 + r) * CDIM + h * 64 + e];
    }
    __syncthreads();

    const int d = tid & 63;
    const int r0 = (tid >> 6) * 16;
    for (int rr = 0; rr < 16; rr++) {
        float s = 0.0f;
#pragma unroll 8
        for (int e = 0; e < 64; e++)
            s = fmaf(ws[r0 + rr][e], cs[d][e], s);
        const long long o = ((long long)b * HID + oc * 64 + r0 + rr) * HID + h * 64 + d;
        const __half h1 = __float2half_rn(s);
        g_M1[o] = h1;
        g_M2[o] = __float2half_rn(s - __half2float(h1));
    }
}

// ---------------------------------------------------------------------------
extern "C" void kernel_launch(void* const* d_in, const int* in_sizes, int n_in,
                              void* d_out, int out_size)
{
    const float* x     = (const float*)d_in[0];   // [8, 512, 4096]
    const float* w_qkv = (const float*)d_in[1];   // [1536, 512]
    const float* w_out = (const float*)d_in[2];   // [512, 512]
    const float* b_out = (const float*)d_in[3];   // [512]
    float* out = (float*)d_out;                   // [8, 512, 4096]

    float *p_kv;
    __half *p_xt1, *p_w1, *p_wqT1, *p_wqT2, *p_M1, *p_M2, *p_N1, *p_N2;
    cudaGetSymbolAddress((void**)&p_kv, g_kv);
    cudaGetSymbolAddress((void**)&p_xt1, g_xt1);
    cudaGetSymbolAddress((void**)&p_w1, g_w1);
    cudaGetSymbolAddress((void**)&p_wqT1, g_wqT1);
    cudaGetSymbolAddress((void**)&p_wqT2, g_wqT2);
    cudaGetSymbolAddress((void**)&p_M1, g_M1);
    cudaGetSymbolAddress((void**)&p_M2, g_M2);
    cudaGetSymbolAddress((void**)&p_N1, g_N1);
    cudaGetSymbolAddress((void**)&p_N2, g_N2);

    int nsm = 148;
    cudaDeviceGetAttribute(&nsm, cudaDevAttrMultiProcessorCount, 0);
    const int grid = 2 * nsm;

    cudaFuncSetAttribute(mma_gemm_persistent,
                         cudaFuncAttributeMaxDynamicSharedMemorySize, GEMM_SMEM);

    // 0) fp16 converts: W_kv (1 limb), x^T (1 limb), Wq^T (2 limbs)
    cvt1_kernel<<<(KV_ROWS * CDIM + 255) / 256, 256>>>(
        w_qkv + (size_t)HID * CDIM, p_w1, KV_ROWS * CDIM);
    transpose_cvt1_kernel<<<dim3(LDIM / 32, CDIM / 32, BATCH), 256>>>(
        x, p_xt1, CDIM, LDIM, (long long)CDIM * LDIM, (long long)LDIM * CDIM);
    transpose_cvt2_kernel<<<dim3(CDIM / 32, HID / 32, 1), 256>>>(
        w_qkv, p_wqT1, p_wqT2, HID, CDIM);

    // 1) kv = W_kv @ x  (plain fp16, 1 MMA/pos)
    mma_gemm_persistent<<<grid, 128, GEMM_SMEM>>>(
        p_w1, nullptr, p_xt1, nullptr, p_kv,
        KV_ROWS / 64, LDIM / 128, BATCH, LDIM, CDIM,
        0LL, (long long)LDIM * CDIM, (long long)KV_ROWS * LDIM, nullptr,
        nullptr, nullptr);

    // 2) softmax over L on k rows
    softmax_kernel<<<BATCH * HID, 256>>>();

    // 3) context partials + deterministic reduce
    context_partial_kernel<<<dim3(CSPLIT, BATCH * HEADS), 256>>>();
    {
        const int total = BATCH * HEADS * DHEAD * DHEAD;
        reduce_ctx_kernel<<<(total + 255) / 256, 256>>>();
    }

    // 4) fold w_out with context -> 2-limb fp16 M
    fold_kernel<<<dim3(8, BATCH * HEADS), 256>>>(w_out);

    // 5) N = M @ Wq  (3-term fp16; tiny, keeps this link near-exact)
    mma_gemm_persistent<<<grid, 128, GEMM_SMEM>>>(
        p_M1, p_M2, p_wqT1, p_wqT2, nullptr,
        HID / 64, CDIM / 128, BATCH, CDIM, HID,
        (long long)HID * HID, 0LL, (long long)HID * CDIM, nullptr,
        p_N1, p_N2);

    // 6) out = N @ x + b_out  (plain fp16, 1 MMA/pos)
    mma_gemm_persistent<<<grid, 128, GEMM_SMEM>>>(
        p_N1, nullptr, p_xt1, nullptr, out,
        HID / 64, LDIM / 128, BATCH, LDIM, CDIM,
        (long long)HID * CDIM, (long long)LDIM * CDIM, (long long)HID * LDIM, b_out,
        nullptr, nullptr);
}

// round 15
// speedup vs baseline: 1.5855x; 1.1709x over previous
#include <cuda_runtime.h>
#include <cuda_fp16.h>
#include <cstdint>

// Problem constants
#define BATCH 8
#define CDIM 512
#define LDIM 4096
#define HEADS 8
#define DHEAD 64
#define HID 512            // HEADS*DHEAD
#define QKV_ROWS 1536      // 3*HID
#define KV_ROWS 1024       // k,v only
#define CSPLIT 32          // n-splits for context partials

// ---------------------------------------------------------------------------
// Scratch (device globals; no allocation allowed)
// ---------------------------------------------------------------------------
__device__ float g_kv[(size_t)BATCH * KV_ROWS * LDIM];      // k rows 0..511, v rows 512..1023
__device__ __half g_xt1[(size_t)BATCH * LDIM * CDIM];       // x^T, 1 fp16 limb
__device__ __half g_w1[(size_t)KV_ROWS * CDIM];             // W_kv, 1 limb
__device__ __half g_wqT1[(size_t)CDIM * HID];               // Wq^T limb 1
__device__ __half g_wqT2[(size_t)CDIM * HID];               // Wq^T limb 2
__device__ float g_part[(size_t)CSPLIT * BATCH * HEADS * DHEAD * DHEAD];
__device__ float g_ctx[(size_t)BATCH * HEADS * DHEAD * DHEAD];
__device__ __half g_M1[(size_t)BATCH * HID * HID];          // M limbs
__device__ __half g_M2[(size_t)BATCH * HID * HID];
__device__ __half g_N1[(size_t)BATCH * HID * CDIM];         // N = M @ Wq limbs
__device__ __half g_N2[(size_t)BATCH * HID * CDIM];

// ---------------------------------------------------------------------------
// PTX helpers (baseline sm_103 — mma.sync fp16 only)
// ---------------------------------------------------------------------------
__device__ __forceinline__ uint32_t smem_to_u32(const void* smem_ptr) {
    uint32_t addr;
    asm("{ .reg .u64 tmp; cvta.to.shared.u64 tmp, %1; cvt.u32.u64 %0, tmp; }"
        : "=r"(addr) : "l"(smem_ptr));
    return addr;
}

#define SMEM_SWIZZLE_128B(byte_offset) \
    ((uint32_t)(byte_offset) ^ ((((uint32_t)(byte_offset)) >> 3) & 0x70u))

__device__ __forceinline__ void cp_async16(uint32_t dst, const void* src) {
    asm volatile("cp.async.cg.shared.global [%0], [%1], 16;"
                 :: "r"(dst), "l"(src) : "memory");
}
#define CP_ASYNC_COMMIT() asm volatile("cp.async.commit_group;" ::: "memory")
#define CP_ASYNC_WAIT(n)  asm volatile("cp.async.wait_group %0;" :: "n"(n) : "memory")

__device__ __forceinline__ void ldsm4(uint32_t* r, uint32_t addr) {
    asm volatile("ldmatrix.sync.aligned.m8n8.x4.shared.b16 {%0,%1,%2,%3}, [%4];"
                 : "=r"(r[0]), "=r"(r[1]), "=r"(r[2]), "=r"(r[3]) : "r"(addr));
}

__device__ __forceinline__ void mma_f16(float* c, const uint32_t* a, const uint32_t* b) {
    asm volatile(
        "mma.sync.aligned.m16n8k16.row.col.f32.f16.f16.f32 "
        "{%0,%1,%2,%3}, {%4,%5,%6,%7}, {%8,%9}, {%0,%1,%2,%3};"
        : "+f"(c[0]), "+f"(c[1]), "+f"(c[2]), "+f"(c[3])
        : "r"(a[0]), "r"(a[1]), "r"(a[2]), "r"(a[3]), "r"(b[0]), "r"(b[1]));
}

// ---------------------------------------------------------------------------
// Specialized 1-term persistent fp16 GEMM: C = A1 @ B1^T (+bias).
// K = 512 (8 chunks of BK=64). CTA = 128 thr (4 warps), tile 64m x 128n,
// warp tile 32x64. 3-stage cp.async ring (24KB/stage, 72KB/CTA -> 3 CTAs/SM),
// ONE __syncthreads per chunk (3-stage ring makes the 2nd barrier redundant:
// barrier at chunk k proves all warps finished reading stage (k-1)%3, which
// is exactly the stage load_chunk(k+2) overwrites).
// ---------------------------------------------------------------------------
#define S1_STAGE 24576
#define S1_OFF_A 0
#define S1_OFF_B 8192
#define S1_SMEM (3 * S1_STAGE)
#define CHUNKS_PER_TILE 8    // K=512 / BK=64

__global__ __launch_bounds__(128, 3)
void gemm1t_persistent(const __half* __restrict__ A1,
                       const __half* __restrict__ B1,
                       float* __restrict__ C,
                       int ntm, int ntn, int nb, int N, int K,
                       long long sA, long long sB, long long sC,
                       const float* __restrict__ bias)
{
    extern __shared__ char smem[];
    const uint32_t sbase = smem_to_u32(smem);

    const int tid = threadIdx.x;
    const int wid = tid >> 5;
    const int lane = tid & 31;
    const int warp_m = wid >> 1;       // 0..1 (32 rows each)
    const int warp_n = wid & 1;        // 0..1 (64 cols each)

    const int ntiles = ntm * ntn * nb;
    const int my_ntiles = (ntiles - (int)blockIdx.x + (int)gridDim.x - 1) / (int)gridDim.x;
    if (my_ntiles <= 0) return;
    const int my_nchunks = my_ntiles * CHUNKS_PER_TILE;

    auto load_chunk = [&](int k) {
        const int t = k >> 3;
        const int tile_lin = (int)blockIdx.x + t * (int)gridDim.x;
        if (tile_lin >= ntiles) { CP_ASYNC_COMMIT(); return; }
        const int nx = tile_lin % ntn;
        const int rest = tile_lin / ntn;
        const int my = rest % ntm;
        const int b = rest / ntm;
        const int bm = my << 6;        // 64-row tiles
        const int bn = nx << 7;        // 128-col tiles
        const int k0 = (k & 7) << 6;
        const __half* pA = A1 + (long long)b * sA;
        const __half* pB = B1 + (long long)b * sB;
        const uint32_t sb = sbase + (uint32_t)(k % 3) * S1_STAGE;
#pragma unroll
        for (int it = 0; it < 4; it++) {
            const int g = it * 128 + tid;
            const int row = g >> 3;
            const int gr = g & 7;
            const uint32_t sw = SMEM_SWIZZLE_128B(row * 128 + gr * 16);
            cp_async16(sb + S1_OFF_A + sw, pA + (long long)(bm + row) * K + k0 + gr * 8);
        }
#pragma unroll
        for (int it = 0; it < 8; it++) {
            const int g = it * 128 + tid;
            const int row = g >> 3;
            const int gr = g & 7;
            const uint32_t sw = SMEM_SWIZZLE_128B(row * 128 + gr * 16);
            cp_async16(sb + S1_OFF_B + sw, pB + (long long)(bn + row) * K + k0 + gr * 8);
        }
        CP_ASYNC_COMMIT();
    };

    float acc[2][8][4];
#pragma unroll
    for (int i = 0; i < 2; i++)
#pragma unroll
        for (int j = 0; j < 8; j++)
#pragma unroll
            for (int r = 0; r < 4; r++) acc[i][j][r] = 0.0f;

    load_chunk(0);
    load_chunk(1);

    for (int k = 0; k < my_nchunks; k++) {
        CP_ASYNC_WAIT(1);
        __syncthreads();          // single barrier per chunk

        const uint32_t sb = sbase + (uint32_t)(k % 3) * S1_STAGE;
#pragma unroll
        for (int ks = 0; ks < 4; ks++) {
            uint32_t b1r[16];
#pragma unroll
            for (int p = 0; p < 4; p++) {
                const int r = warp_n * 64 + p * 16 + ((lane >> 4) & 1) * 8 + (lane & 7);
                const int cb = ks * 32 + ((lane >> 3) & 1) * 16;
                ldsm4(b1r + p * 4, sb + S1_OFF_B + SMEM_SWIZZLE_128B(r * 128 + cb));
            }
#pragma unroll
            for (int i = 0; i < 2; i++) {
                const int r = warp_m * 32 + i * 16 + ((lane >> 3) & 1) * 8 + (lane & 7);
                const int cb = ks * 32 + ((lane >> 4) & 1) * 16;
                uint32_t a1[4];
                ldsm4(a1, sb + S1_OFF_A + SMEM_SWIZZLE_128B(r * 128 + cb));
#pragma unroll
                for (int j = 0; j < 8; j++)
                    mma_f16(acc[i][j], a1, b1r + (j >> 1) * 4 + (j & 1) * 2);
            }
        }

        load_chunk(k + 2);        // writes stage (k+2)%3 == (k-1)%3: safe

        if ((k & 7) == 7) {
            const int t = k >> 3;
            const int tile_lin = (int)blockIdx.x + t * (int)gridDim.x;
            const int nx = tile_lin % ntn;
            const int rest = tile_lin / ntn;
            const int my = rest % ntm;
            const int b = rest / ntm;
            const int bm = my << 6;
            const int bn = nx << 7;
            float* pC = C + (long long)b * sC;
#pragma unroll
            for (int i = 0; i < 2; i++) {
                const int m0 = bm + warp_m * 32 + i * 16 + (lane >> 2);
                const float bv0 = bias ? bias[m0] : 0.0f;
                const float bv1 = bias ? bias[m0 + 8] : 0.0f;
#pragma unroll
                for (int j = 0; j < 8; j++) {
                    const int n0 = bn + warp_n * 64 + j * 8 + (lane & 3) * 2;
                    float2 v0, v1;
                    v0.x = acc[i][j][0] + bv0;  v0.y = acc[i][j][1] + bv0;
                    v1.x = acc[i][j][2] + bv1;  v1.y = acc[i][j][3] + bv1;
                    *(float2*)(pC + (long long)m0 * N + n0) = v0;
                    *(float2*)(pC + (long long)(m0 + 8) * N + n0) = v1;
                    acc[i][j][0] = 0.0f; acc[i][j][1] = 0.0f;
                    acc[i][j][2] = 0.0f; acc[i][j][3] = 0.0f;
                }
            }
        }
    }
}

// ---------------------------------------------------------------------------
// General multi-limb persistent GEMM (used only for the tiny N = M @ Wq,
// 3-term: M1Wq1 + M2Wq1 + M1Wq2, 2-limb fp16 output). Same as round 14.
// ---------------------------------------------------------------------------
#define STAGE_BYTES 49152
#define OFF_A1 0
#define OFF_A2 8192
#define OFF_B1 16384
#define OFF_B2 32768
#define GEMM_SMEM (2 * STAGE_BYTES)

__global__ __launch_bounds__(128, 2)
void mma_gemm_persistent(const __half* __restrict__ A1,
                         const __half* __restrict__ A2,
                         const __half* __restrict__ B1,
                         const __half* __restrict__ B2,
                         float* __restrict__ C,
                         int ntm, int ntn, int nb, int N, int K,
                         long long sA, long long sB, long long sC,
                         const float* __restrict__ bias,
                         __half* __restrict__ O1,
                         __half* __restrict__ O2)
{
    extern __shared__ char smem[];
    const uint32_t sbase = smem_to_u32(smem);

    const int tid = threadIdx.x;
    const int wid = tid >> 5;
    const int lane = tid & 31;
    const int warp_m = wid >> 1;
    const int warp_n = wid & 1;
    const bool has_a2 = (A2 != nullptr);
    const bool has_b2 = (B2 != nullptr);

    const int ntiles = ntm * ntn * nb;
    const int my_ntiles = (ntiles - (int)blockIdx.x + (int)gridDim.x - 1) / (int)gridDim.x;
    if (my_ntiles <= 0) return;
    const int my_nchunks = my_ntiles * CHUNKS_PER_TILE;

    auto load_chunk = [&](int k) {
        const int t = k >> 3;
        const int tile_lin = (int)blockIdx.x + t * (int)gridDim.x;
        if (tile_lin >= ntiles) { CP_ASYNC_COMMIT(); return; }
        const int nx = tile_lin % ntn;
        const int rest = tile_lin / ntn;
        const int my = rest % ntm;
        const int b = rest / ntm;
        const int bm = my << 6;
        const int bn = nx << 7;
        const int k0 = (k & 7) << 6;
        const __half* pA1 = A1 + (long long)b * sA;
        const __half* pB1 = B1 + (long long)b * sB;
        const uint32_t sb = sbase + (uint32_t)(k & 1) * STAGE_BYTES;
#pragma unroll
        for (int it = 0; it < 4; it++) {
            const int g = it * 128 + tid;
            const int row = g >> 3;
            const int gr = g & 7;
            const uint32_t sw = SMEM_SWIZZLE_128B(row * 128 + gr * 16);
            const long long aoff = (long long)(bm + row) * K + k0 + gr * 8;
            cp_async16(sb + OFF_A1 + sw, pA1 + aoff);
        }
        if (has_a2) {
            const __half* pA2 = A2 + (long long)b * sA;
#pragma unroll
            for (int it = 0; it < 4; it++) {
                const int g = it * 128 + tid;
                const int row = g >> 3;
                const int gr = g & 7;
                const uint32_t sw = SMEM_SWIZZLE_128B(row * 128 + gr * 16);
                const long long aoff = (long long)(bm + row) * K + k0 + gr * 8;
                cp_async16(sb + OFF_A2 + sw, pA2 + aoff);
            }
        }
#pragma unroll
        for (int it = 0; it < 8; it++) {
            const int g = it * 128 + tid;
            const int row = g >> 3;
            const int gr = g & 7;
            const uint32_t sw = SMEM_SWIZZLE_128B(row * 128 + gr * 16);
            const long long boff = (long long)(bn + row) * K + k0 + gr * 8;
            cp_async16(sb + OFF_B1 + sw, pB1 + boff);
        }
        if (has_b2) {
            const __half* pB2 = B2 + (long long)b * sB;
#pragma unroll
            for (int it = 0; it < 8; it++) {
                const int g = it * 128 + tid;
                const int row = g >> 3;
                const int gr = g & 7;
                const uint32_t sw = SMEM_SWIZZLE_128B(row * 128 + gr * 16);
                const long long boff = (long long)(bn + row) * K + k0 + gr * 8;
                cp_async16(sb + OFF_B2 + sw, pB2 + boff);
            }
        }
        CP_ASYNC_COMMIT();
    };

    float acc[2][8][4];
#pragma unroll
    for (int i = 0; i < 2; i++)
#pragma unroll
        for (int j = 0; j < 8; j++)
#pragma unroll
            for (int r = 0; r < 4; r++) acc[i][j][r] = 0.0f;

    load_chunk(0);
    load_chunk(1);

    for (int k = 0; k < my_nchunks; k++) {
        CP_ASYNC_WAIT(1);
        __syncthreads();

        const uint32_t sb = sbase + (uint32_t)(k & 1) * STAGE_BYTES;
#pragma unroll
        for (int ks = 0; ks < 4; ks++) {
            uint32_t b1r[16];
#pragma unroll
            for (int p = 0; p < 4; p++) {
                const int r = warp_n * 64 + p * 16 + ((lane >> 4) & 1) * 8 + (lane & 7);
                const int cb = ks * 32 + ((lane >> 3) & 1) * 16;
                ldsm4(b1r + p * 4, sb + OFF_B1 + SMEM_SWIZZLE_128B(r * 128 + cb));
            }
            uint32_t b2r[16];
            if (has_b2) {
#pragma unroll
                for (int p = 0; p < 4; p++) {
                    const int r = warp_n * 64 + p * 16 + ((lane >> 4) & 1) * 8 + (lane & 7);
                    const int cb = ks * 32 + ((lane >> 3) & 1) * 16;
                    ldsm4(b2r + p * 4, sb + OFF_B2 + SMEM_SWIZZLE_128B(r * 128 + cb));
                }
            }
#pragma unroll
            for (int i = 0; i < 2; i++) {
                const int r = warp_m * 32 + i * 16 + ((lane >> 3) & 1) * 8 + (lane & 7);
                const int cb = ks * 32 + ((lane >> 4) & 1) * 16;
                const uint32_t adr = sb + OFF_A1 + SMEM_SWIZZLE_128B(r * 128 + cb);
                uint32_t a1[4];
                ldsm4(a1, adr);
#pragma unroll
                for (int j = 0; j < 8; j++)
                    mma_f16(acc[i][j], a1, b1r + (j >> 1) * 4 + (j & 1) * 2);
                if (has_a2) {
                    uint32_t a2[4];
                    ldsm4(a2, adr + (OFF_A2 - OFF_A1));
#pragma unroll
                    for (int j = 0; j < 8; j++)
                        mma_f16(acc[i][j], a2, b1r + (j >> 1) * 4 + (j & 1) * 2);
                }
                if (has_b2) {
#pragma unroll
                    for (int j = 0; j < 8; j++)
                        mma_f16(acc[i][j], a1, b2r + (j >> 1) * 4 + (j & 1) * 2);
                }
            }
        }
        __syncthreads();
        load_chunk(k + 2);

        if ((k & 7) == 7) {
            const int t = k >> 3;
            const int tile_lin = (int)blockIdx.x + t * (int)gridDim.x;
            const int nx = tile_lin % ntn;
            const int rest = tile_lin / ntn;
            const int my = rest % ntm;
            const int b = rest / ntm;
            const int bm = my << 6;
            const int bn = nx << 7;
            if (O1 == nullptr) {
                float* pC = C + (long long)b * sC;
#pragma unroll
                for (int i = 0; i < 2; i++) {
                    const int m0 = bm + warp_m * 32 + i * 16 + (lane >> 2);
                    const float bv0 = bias ? bias[m0] : 0.0f;
                    const float bv1 = bias ? bias[m0 + 8] : 0.0f;
#pragma unroll
                    for (int j = 0; j < 8; j++) {
                        const int n0 = bn + warp_n * 64 + j * 8 + (lane & 3) * 2;
                        float2 v0, v1;
                        v0.x = acc[i][j][0] + bv0;  v0.y = acc[i][j][1] + bv0;
                        v1.x = acc[i][j][2] + bv1;  v1.y = acc[i][j][3] + bv1;
                        *(float2*)(pC + (long long)m0 * N + n0) = v0;
                        *(float2*)(pC + (long long)(m0 + 8) * N + n0) = v1;
                        acc[i][j][0] = 0.0f; acc[i][j][1] = 0.0f;
                        acc[i][j][2] = 0.0f; acc[i][j][3] = 0.0f;
                    }
                }
            } else {
                __half* p1 = O1 + (long long)b * sC;
                __half* p2 = O2 + (long long)b * sC;
#pragma unroll
                for (int i = 0; i < 2; i++) {
                    const int m0 = bm + warp_m * 32 + i * 16 + (lane >> 2);
#pragma unroll
                    for (int j = 0; j < 8; j++) {
                        const int n0 = bn + warp_n * 64 + j * 8 + (lane & 3) * 2;
#pragma unroll
                        for (int r = 0; r < 4; r++) {
                            const int mm = m0 + (r >> 1) * 8;
                            const int nn = n0 + (r & 1);
                            const float v = acc[i][j][r];
                            const __half h1 = __float2half_rn(v);
                            p1[(long long)mm * N + nn] = h1;
                            p2[(long long)mm * N + nn] = __float2half_rn(v - __half2float(h1));
                            acc[i][j][r] = 0.0f;
                        }
                    }
                }
            }
        }
    }
}

// ---------------------------------------------------------------------------
// Transpose + fp16 convert (1 limb): in fp32 [R, L] -> out [L, R]
// ---------------------------------------------------------------------------
__global__ __launch_bounds__(256) void transpose_cvt1_kernel(
    const float* __restrict__ in, __half* __restrict__ out,
    int R, int L, long long inStride, long long outStride)
{
    const int b = blockIdx.z;
    in += (long long)b * inStride;
    out += (long long)b * outStride;

    __shared__ float t[32][33];
    const int r0 = blockIdx.y * 32;
    const int c0 = blockIdx.x * 32;
    const int tx = threadIdx.x & 31;
    const int ty = threadIdx.x >> 5;

#pragma unroll
    for (int i = 0; i < 4; i++)
        t[ty + i * 8][tx] = in[(long long)(r0 + ty + i * 8) * L + c0 + tx];
    __syncthreads();
#pragma unroll
    for (int i = 0; i < 4; i++) {
        const float v = t[tx][ty + i * 8];
        out[(long long)(c0 + ty + i * 8) * R + r0 + tx] = __float2half_rn(v);
    }
}

// Transpose + fp16 2-limb split: in fp32 [R, L] -> limbs [L, R]
__global__ __launch_bounds__(256) void transpose_cvt2_kernel(
    const float* __restrict__ in,
    __half* __restrict__ o1, __half* __restrict__ o2, int R, int L)
{
    __shared__ float t[32][33];
    const int r0 = blockIdx.y * 32;
    const int c0 = blockIdx.x * 32;
    const int tx = threadIdx.x & 31;
    const int ty = threadIdx.x >> 5;

#pragma unroll
    for (int i = 0; i < 4; i++)
        t[ty + i * 8][tx] = in[(long long)(r0 + ty + i * 8) * L + c0 + tx];
    __syncthreads();
#pragma unroll
    for (int i = 0; i < 4; i++) {
        const float v = t[tx][ty + i * 8];
        const __half h1 = __float2half_rn(v);
        const long long o = (long long)(c0 + ty + i * 8) * R + r0 + tx;
        o1[o] = h1;
        o2[o] = __float2half_rn(v - __half2float(h1));
    }
}

// Plain fp16 convert (1 limb)
__global__ __launch_bounds__(256) void cvt1_kernel(
    const float* __restrict__ in, __half* __restrict__ o1, int n)
{
    const int i = blockIdx.x * blockDim.x + threadIdx.x;
    if (i < n) o1[i] = __float2half_rn(in[i]);
}

// ---------------------------------------------------------------------------
// Row softmax over L=4096 on k rows (rows 0..511 of g_kv per batch)
// ---------------------------------------------------------------------------
__global__ __launch_bounds__(256) void softmax_kernel()
{
    const int row = blockIdx.x;
    const int b = row >> 9;
    const int r = row & 511;
    float* p = g_kv + (long long)b * KV_ROWS * LDIM + (long long)r * LDIM;

    const int tid = threadIdx.x;
    __shared__ float red[256];

    float4 v[4];
#pragma unroll
    for (int i = 0; i < 4; i++)
        v[i] = *(const float4*)(p + i * 1024 + tid * 4);

    float vmax = -1e30f;
#pragma unroll
    for (int i = 0; i < 4; i++)
        vmax = fmaxf(vmax, fmaxf(fmaxf(v[i].x, v[i].y), fmaxf(v[i].z, v[i].w)));
    red[tid] = vmax;
    __syncthreads();
    for (int s = 128; s > 0; s >>= 1) {
        if (tid < s) red[tid] = fmaxf(red[tid], red[tid + s]);
        __syncthreads();
    }
    vmax = red[0];
    __syncthreads();

    float lsum = 0.0f;
#pragma unroll
    for (int i = 0; i < 4; i++) {
        v[i].x = expf(v[i].x - vmax); lsum += v[i].x;
        v[i].y = expf(v[i].y - vmax); lsum += v[i].y;
        v[i].z = expf(v[i].z - vmax); lsum += v[i].z;
        v[i].w = expf(v[i].w - vmax); lsum += v[i].w;
    }
    red[tid] = lsum;
    __syncthreads();
    for (int s = 128; s > 0; s >>= 1) {
        if (tid < s) red[tid] += red[tid + s];
        __syncthreads();
    }
    const float inv = 1.0f / red[0];

#pragma unroll
    for (int i = 0; i < 4; i++) {
        v[i].x *= inv; v[i].y *= inv; v[i].z *= inv; v[i].w *= inv;
        *(float4*)(p + i * 1024 + tid * 4) = v[i];
    }
}

// ---------------------------------------------------------------------------
// Context partials + reduce + fold (fp32)
// ---------------------------------------------------------------------------
__global__ __launch_bounds__(256) void context_partial_kernel()
{
    const int split = blockIdx.x;
    const int bh = blockIdx.y;
    const int b = bh >> 3, h = bh & 7;

    const float* kbase = g_kv + (long long)b * KV_ROWS * LDIM + (long long)(h * DHEAD) * LDIM;
    const float* vbase = g_kv + (long long)b * KV_ROWS * LDIM + (long long)(HID + h * DHEAD) * LDIM;

    __shared__ float Ks[64][65];
    __shared__ float Vs[64][65];

    const int tid = threadIdx.x;
    const int td = (tid >> 4) * 4;
    const int te = (tid & 15) * 4;

    float acc[4][4];
#pragma unroll
    for (int i = 0; i < 4; i++)
#pragma unroll
        for (int j = 0; j < 4; j++) acc[i][j] = 0.0f;

    const int chunk = LDIM / CSPLIT;
    for (int sub = 0; sub < chunk / 64; sub++) {
        const int n0 = split * chunk + sub * 64;
        for (int i = tid; i < 1024; i += 256) {
            const int r = i >> 4, c = (i & 15) * 4;
            float4 kv = *(const float4*)(kbase + (long long)r * LDIM + n0 + c);
            Ks[r][c] = kv.x; Ks[r][c + 1] = kv.y; Ks[r][c + 2] = kv.z; Ks[r][c + 3] = kv.w;
            float4 vv = *(const float4*)(vbase + (long long)r * LDIM + n0 + c);
            Vs[r][c] = vv.x; Vs[r][c + 1] = vv.y; Vs[r][c + 2] = vv.z; Vs[r][c + 3] = vv.w;
        }
        __syncthreads();

#pragma unroll 8
        for (int n = 0; n < 64; n++) {
            float kr[4], vr[4];
#pragma unroll
            for (int i = 0; i < 4; i++) kr[i] = Ks[td + i][n];
#pragma unroll
            for (int j = 0; j < 4; j++) vr[j] = Vs[te + j][n];
#pragma unroll
            for (int i = 0; i < 4; i++)
#pragma unroll
                for (int j = 0; j < 4; j++)
                    acc[i][j] = fmaf(kr[i], vr[j], acc[i][j]);
        }
        __syncthreads();
    }

    float* pout = g_part + ((long long)split * 64 + bh) * (DHEAD * DHEAD);
#pragma unroll
    for (int i = 0; i < 4; i++)
#pragma unroll
        for (int j = 0; j < 4; j++)
            pout[(td + i) * DHEAD + (te + j)] = acc[i][j];
}

__global__ __launch_bounds__(256) void reduce_ctx_kernel()
{
    const int i = blockIdx.x * blockDim.x + threadIdx.x;
    const int total = BATCH * HEADS * DHEAD * DHEAD;
    if (i < total) {
        float s = 0.0f;
#pragma unroll
        for (int sp = 0; sp < CSPLIT; sp++)
            s += g_part[(long long)sp * total + i];
        g_ctx[i] = s;
    }
}

// fold: writes 2-limb fp16 M directly
__global__ __launch_bounds__(256) void fold_kernel(const float* __restrict__ w_out)
{
    const int oc = blockIdx.x;
    const int bh = blockIdx.y;
    const int b = bh >> 3, h = bh & 7;

    __shared__ float cs[64][65];
    __shared__ float ws[64][65];

    const int tid = threadIdx.x;
    for (int i = tid; i < 4096; i += 256) {
        const int d = i >> 6, e = i & 63;
        cs[d][e] = g_ctx[((long long)bh * 64 + d) * 64 + e];
    }
    for (int i = tid; i < 4096; i += 256) {
        const int r = i >> 6, e = i & 63;
        ws[r][e] = w_out[(long long)(oc * 64 + r) * CDIM + h * 64 + e];
    }
    __syncthreads();

    const int d = tid & 63;
    const int r0 = (tid >> 6) * 16;
    for (int rr = 0; rr < 16; rr++) {
        float s = 0.0f;
#pragma unroll 8
        for (int e = 0; e < 64; e++)
            s = fmaf(ws[r0 + rr][e], cs[d][e], s);
        const long long o = ((long long)b * HID + oc * 64 + r0 + rr) * HID + h * 64 + d;
        const __half h1 = __float2half_rn(s);
        g_M1[o] = h1;
        g_M2[o] = __float2half_rn(s - __half2float(h1));
    }
}

// ---------------------------------------------------------------------------
extern "C" void kernel_launch(void* const* d_in, const int* in_sizes, int n_in,
                              void* d_out, int out_size)
{
    const float* x     = (const float*)d_in[0];   // [8, 512, 4096]
    const float* w_qkv = (const float*)d_in[1];   // [1536, 512]
    const float* w_out = (const float*)d_in[2];   // [512, 512]
    const float* b_out = (const float*)d_in[3];   // [512]
    float* out = (float*)d_out;                   // [8, 512, 4096]

    float *p_kv;
    __half *p_xt1, *p_w1, *p_wqT1, *p_wqT2, *p_M1, *p_M2, *p_N1, *p_N2;
    cudaGetSymbolAddress((void**)&p_kv, g_kv);
    cudaGetSymbolAddress((void**)&p_xt1, g_xt1);
    cudaGetSymbolAddress((void**)&p_w1, g_w1);
    cudaGetSymbolAddress((void**)&p_wqT1, g_wqT1);
    cudaGetSymbolAddress((void**)&p_wqT2, g_wqT2);
    cudaGetSymbolAddress((void**)&p_M1, g_M1);
    cudaGetSymbolAddress((void**)&p_M2, g_M2);
    cudaGetSymbolAddress((void**)&p_N1, g_N1);
    cudaGetSymbolAddress((void**)&p_N2, g_N2);

    int nsm = 148;
    cudaDeviceGetAttribute(&nsm, cudaDevAttrMultiProcessorCount, 0);

    cudaFuncSetAttribute(gemm1t_persistent,
                         cudaFuncAttributeMaxDynamicSharedMemorySize, S1_SMEM);
    cudaFuncSetAttribute(mma_gemm_persistent,
                         cudaFuncAttributeMaxDynamicSharedMemorySize, GEMM_SMEM);

    // 0) fp16 converts: W_kv (1 limb), x^T (1 limb), Wq^T (2 limbs)
    cvt1_kernel<<<(KV_ROWS * CDIM + 255) / 256, 256>>>(
        w_qkv + (size_t)HID * CDIM, p_w1, KV_ROWS * CDIM);
    transpose_cvt1_kernel<<<dim3(LDIM / 32, CDIM / 32, BATCH), 256>>>(
        x, p_xt1, CDIM, LDIM, (long long)CDIM * LDIM, (long long)LDIM * CDIM);
    transpose_cvt2_kernel<<<dim3(CDIM / 32, HID / 32, 1), 256>>>(
        w_qkv, p_wqT1, p_wqT2, HID, CDIM);

    // 1) kv = W_kv @ x  (1-term fp16, 3 CTAs/SM)
    gemm1t_persistent<<<3 * nsm, 128, S1_SMEM>>>(
        p_w1, p_xt1, p_kv,
        KV_ROWS / 64, LDIM / 128, BATCH, LDIM, CDIM,
        0LL, (long long)LDIM * CDIM, (long long)KV_ROWS * LDIM, nullptr);

    // 2) softmax over L on k rows
    softmax_kernel<<<BATCH * HID, 256>>>();

    // 3) context partials + deterministic reduce
    context_partial_kernel<<<dim3(CSPLIT, BATCH * HEADS), 256>>>();
    {
        const int total = BATCH * HEADS * DHEAD * DHEAD;
        reduce_ctx_kernel<<<(total + 255) / 256, 256>>>();
    }

    // 4) fold w_out with context -> 2-limb fp16 M
    fold_kernel<<<dim3(8, BATCH * HEADS), 256>>>(w_out);

    // 5) N = M @ Wq  (3-term fp16; tiny, keeps this link near-exact)
    mma_gemm_persistent<<<2 * nsm, 128, GEMM_SMEM>>>(
        p_M1, p_M2, p_wqT1, p_wqT2, nullptr,
        HID / 64, CDIM / 128, BATCH, CDIM, HID,
        (long long)HID * HID, 0LL, (long long)HID * CDIM, nullptr,
        p_N1, p_N2);

    // 6) out = N @ x + b_out  (1-term fp16, 3 CTAs/SM)
    gemm1t_persistent<<<3 * nsm, 128, S1_SMEM>>>(
        p_N1, p_xt1, out,
        HID / 64, LDIM / 128, BATCH, LDIM, CDIM,
        (long long)HID * CDIM, (long long)LDIM * CDIM, (long long)HID * LDIM, b_out);
}